// round 9
// baseline (speedup 1.0000x reference)
#include <cuda_runtime.h>
#include <cuda_bf16.h>
#include <math.h>
#include <stdint.h>

#define E_EDGES 100000
#define S_MEM   16
#define D_DIM   128
#define C_CLS   6
#define M_IND   4
#define NTH     512
#define SCALE_INV 0.08838834764831845f

// ---- shared-region offsets (bytes) ----
#define OFF_BIAS 0          // f32[6][128]  = 3072
#define OFF_IQ   3072       // f32[512]     = 2048
#define OFF_IQB  5120       // f32[16]      = 64
#define OFF_WOUT 5184       // f32[776]     = 3104  (ends 8288)
#define OFF_G0   8320
// ---- per-group offsets ----
#define GOFF_XH  0          // bf16 image 64x128 = 16384
#define GOFF_XL  16384
#define GOFF_SF  32768      // f32 [64][132] = 33792
#define SF_STR   132
#define GOFF_SSM 66560      // f32 [16][132] = 8448
#define GOFF_SCR 75008      // f32 [1024]    = 4096
#define GSZ      79104
#define SMEM_TOTAL (OFF_G0 + 2*GSZ)   // 166528

__device__ __align__(16) float g_Iq[M_IND * D_DIM];
__device__ __align__(16) float g_Iqb[16];
// frag-ordered weights: [w][hl][ks(8)][nt8(16)][lane(32)] as uint2
// widx: 0=Wk0 1=Wv0 2=Wq1 3=Wo0 4=Wk1 5=Wv1 6=Wo1
__device__ __align__(16) uint2 g_WF[7 * 2 * 8 * 16 * 32];

// image byte offset: row r (0..63), col c (0..127); 16B-chunk XOR swizzle
__host__ __device__ __forceinline__ int imgoff(int r, int c) {
    return r * 256 + (((c >> 3) ^ (r & 7)) << 4) + ((c & 7) << 1);
}

__device__ __forceinline__ uint32_t cvta_s(const void* p) {
    uint32_t a;
    asm("{ .reg .u64 t; cvta.to.shared.u64 t, %1; cvt.u32.u64 %0, t; }" : "=r"(a) : "l"(p));
    return a;
}
__device__ __forceinline__ void gbar(int g) {
    asm volatile("bar.sync %0, %1;" :: "r"(g + 1), "r"(256) : "memory");
}
__device__ __forceinline__ void ldsm4(uint32_t* a, uint32_t addr) {
    asm volatile("ldmatrix.sync.aligned.m8n8.x4.shared.b16 {%0,%1,%2,%3}, [%4];"
        : "=r"(a[0]), "=r"(a[1]), "=r"(a[2]), "=r"(a[3]) : "r"(addr));
}
__device__ __forceinline__ void mma16816(float* c, const uint32_t* a, uint32_t b0, uint32_t b1) {
    asm volatile("mma.sync.aligned.m16n8k16.row.col.f32.bf16.bf16.f32 "
        "{%0,%1,%2,%3}, {%4,%5,%6,%7}, {%8,%9}, {%0,%1,%2,%3};"
        : "+f"(c[0]), "+f"(c[1]), "+f"(c[2]), "+f"(c[3])
        : "r"(a[0]), "r"(a[1]), "r"(a[2]), "r"(a[3]), "r"(b0), "r"(b1));
}
__device__ __forceinline__ void img_st(char* gm, int r, int c, float v) {
    int i = imgoff(r, c);
    __nv_bfloat16 h = __float2bfloat16(v);
    *(__nv_bfloat16*)(gm + GOFF_XH + i) = h;
    *(__nv_bfloat16*)(gm + GOFF_XL + i) = __float2bfloat16(v - __bfloat162float(h));
}
__device__ __forceinline__ void img_st2(char* gm, int r, int c, float v0, float v1) {
    int i = imgoff(r, c);
    __nv_bfloat162 h, l;
    h.x = __float2bfloat16(v0); h.y = __float2bfloat16(v1);
    l.x = __float2bfloat16(v0 - __bfloat162float(h.x));
    l.y = __float2bfloat16(v1 - __bfloat162float(h.y));
    *(__nv_bfloat162*)(gm + GOFF_XH + i) = h;
    *(__nv_bfloat162*)(gm + GOFF_XL + i) = l;
}

// ---------------- prologs ----------------
__global__ void iq_kernel(const float* __restrict__ I, const float* __restrict__ Wq,
                          const float* __restrict__ bq) {
    int idx = blockIdx.x * blockDim.x + threadIdx.x;
    if (idx >= M_IND * D_DIM) return;
    int qi = idx / D_DIM, d = idx % D_DIM;
    float acc = bq[d];
    for (int k = 0; k < D_DIM; k++) acc += I[qi * D_DIM + k] * Wq[k * D_DIM + d];
    g_Iq[idx] = acc;
}
__global__ void iqb_kernel(const float* __restrict__ bk0) {
    int t = threadIdx.x;
    if (t < 16) {
        int qi = t >> 2, h = t & 3;
        float s = 0.f;
        for (int j = 0; j < 32; j++) s += g_Iq[qi * 128 + h * 32 + j] * bk0[h * 32 + j];
        g_Iqb[t] = s;
    }
}
__device__ __forceinline__ uint32_t pack_bf2(float a, float b) {
    __nv_bfloat162 p;
    p.x = __float2bfloat16(a); p.y = __float2bfloat16(b);
    return *(uint32_t*)&p;
}
__global__ void wconv_kernel(const float* W0, const float* W1, const float* W2, const float* W3,
                             const float* W4, const float* W5, const float* W6) {
    const float* W;
    int w = blockIdx.x;
    switch (w) { case 0: W = W0; break; case 1: W = W1; break; case 2: W = W2; break;
                 case 3: W = W3; break; case 4: W = W4; break; case 5: W = W5; break;
                 default: W = W6; }
    for (int idx = threadIdx.x; idx < 2 * 8 * 16 * 32; idx += blockDim.x) {
        int lane = idx & 31;
        int nt8  = (idx >> 5) & 15;
        int ks   = (idx >> 9) & 7;
        int hl   = idx >> 12;
        int n  = nt8 * 8 + (lane >> 2);
        int k0 = ks * 16 + (lane & 3) * 2;
        float a0 = W[k0 * 128 + n],       a1 = W[(k0 + 1) * 128 + n];
        float a2 = W[(k0 + 8) * 128 + n], a3 = W[(k0 + 9) * 128 + n];
        if (hl) {   // lo residuals
            a0 -= __bfloat162float(__float2bfloat16(a0));
            a1 -= __bfloat162float(__float2bfloat16(a1));
            a2 -= __bfloat162float(__float2bfloat16(a2));
            a3 -= __bfloat162float(__float2bfloat16(a3));
        }
        uint2 v;
        v.x = pack_bf2(a0, a1);
        v.y = pack_bf2(a2, a3);
        g_WF[((w * 2 + hl) * 8 + ks) * 16 * 32 + nt8 * 32 + lane] = v;
    }
}

// ---- 64x128x128 GEMM, 3-pass bf16 split; 8 warps: rowgroup wl>>1, colgroup wl&1 ----
__device__ __forceinline__ void gemm64(uint32_t xh, uint32_t xl, const uint2* __restrict__ wf,
                                       int wl, int lane, float acc[8][4]) {
    const int rg = wl >> 1, cg = wl & 1;
    const int lr = lane & 15, lh = lane >> 4;
    const uint2* __restrict__ wfl = wf + 8 * 16 * 32;
#pragma unroll
    for (int ks = 0; ks < 8; ks++) {
        int r = rg * 16 + lr;
        uint32_t off = (uint32_t)(r * 256 + (((ks * 2 + lh) ^ (r & 7)) << 4));
        uint32_t ah[4], al[4];
        ldsm4(ah, xh + off);
        ldsm4(al, xl + off);
        uint2 bh[8], bl[8];
#pragma unroll
        for (int nt = 0; nt < 8; nt++) {
            int i = (ks * 16 + cg * 8 + nt) * 32 + lane;
            bh[nt] = wf[i];
            bl[nt] = wfl[i];
        }
#pragma unroll
        for (int nt = 0; nt < 8; nt++) {
            mma16816(acc[nt], ah, bh[nt].x, bh[nt].y);
            mma16816(acc[nt], al, bh[nt].x, bh[nt].y);
            mma16816(acc[nt], ah, bl[nt].x, bl[nt].y);
        }
    }
}

// ---- 16x128x128 GEMM; 8 warps: each owns 16 cols (nt8 = wl*2, wl*2+1) ----
__device__ __forceinline__ void gemm16(uint32_t xh, uint32_t xl, const uint2* __restrict__ wf,
                                       int wl, int lane, float acc[2][4]) {
    const int lr = lane & 15, lh = lane >> 4;
    const uint2* __restrict__ wfl = wf + 8 * 16 * 32;
#pragma unroll
    for (int ks = 0; ks < 8; ks++) {
        uint32_t off = (uint32_t)(lr * 256 + (((ks * 2 + lh) ^ (lr & 7)) << 4));
        uint32_t ah[4], al[4];
        ldsm4(ah, xh + off);
        ldsm4(al, xl + off);
#pragma unroll
        for (int nt = 0; nt < 2; nt++) {
            int i = (ks * 16 + wl * 2 + nt) * 32 + lane;
            uint2 bh = wf[i], bl = wfl[i];
            mma16816(acc[nt], ah, bh.x, bh.y);
            mma16816(acc[nt], al, bh.x, bh.y);
            mma16816(acc[nt], ah, bl.x, bl.y);
        }
    }
}

extern "C" __global__ void __launch_bounds__(NTH)
whatsnet_mma2(const float* __restrict__ vfeat, const int* __restrict__ member_idx,
              const int* __restrict__ labels,
              const float* __restrict__ Wout, const float* __restrict__ bout,
              const float* __restrict__ bv0, const float* __restrict__ bo0,
              const float* __restrict__ bq1, const float* __restrict__ bk1,
              const float* __restrict__ bv1, const float* __restrict__ bo1,
              float* __restrict__ out, int n_nodes, long long out_capacity)
{
    extern __shared__ char sm[];
    const int tid = threadIdx.x;
    const int lane = tid & 31;
    const int g = tid >> 8;           // group 0/1
    const int tl = tid & 255;         // tid within group
    const int wl = (tid >> 5) & 7;    // warp within group
    const int rowbase = blockIdx.x * 128 + g * 64;

    char* gm = sm + OFF_G0 + g * GSZ;
    const uint32_t sb = cvta_s(sm);
    const uint32_t xh = sb + OFF_G0 + g * GSZ + GOFF_XH;
    const uint32_t xl = xh + 16384;

    float* sF   = (float*)(gm + GOFF_SF);
    float* sSm  = (float*)(gm + GOFF_SSM);
    float* sScr = (float*)(gm + GOFF_SCR);
    float* sV1f = (float*)(gm + GOFF_XH + 4096);   // 16x128 f32, rows 16..47 of XH (dead then)
    float* sBias= (float*)(sm + OFF_BIAS);
    float* sIq  = (float*)(sm + OFF_IQ);
    float* sIqb = (float*)(sm + OFF_IQB);
    float* sWo  = (float*)(sm + OFF_WOUT);

    // shared constants (whole CTA)
    if (tid < 128) {
        sBias[0 * 128 + tid] = bv0[tid];
        sBias[1 * 128 + tid] = bo0[tid];
        sBias[2 * 128 + tid] = bq1[tid];
        sBias[3 * 128 + tid] = bk1[tid];
        sBias[4 * 128 + tid] = bv1[tid];
        sBias[5 * 128 + tid] = bo1[tid];
    }
    for (int i = tid; i < 512; i += NTH) sIq[i] = g_Iq[i];
    if (tid < 16) sIqb[tid] = g_Iqb[tid];
    for (int i = tid; i < 768; i += NTH) sWo[i] = Wout[i];
    if (tid < 6) sWo[768 + tid] = bout[tid];

    // gather -> group X image (64 rows)
    for (int r = wl; r < 64; r += 8) {
        int n = member_idx[rowbase + r];
        if (n < 0) n = 0;
        if (n >= n_nodes) n = n_nodes - 1;
        const float* src = vfeat + (size_t)n * D_DIM;
#pragma unroll
        for (int k = 0; k < 4; k++) {
            int c = lane + k * 32;
            img_st(gm, r, c, src[c]);
        }
    }
    __syncthreads();   // ONLY full-CTA sync; groups diverge after this

    const int l4 = lane >> 2, c2 = (lane & 3) * 2;
    const int rg = wl >> 1, cg = wl & 1;
    const uint2* WF = g_WF;

    // ===== K0 = X@Wk0 -> sF raw =====
    {
        float acc[8][4] = {};
        gemm64(xh, xl, WF + 0 * 8192, wl, lane, acc);
#pragma unroll
        for (int nt = 0; nt < 8; nt++) {
            int r = rg * 16 + l4, c = cg * 64 + nt * 8 + c2;
            sF[r * SF_STR + c]       = acc[nt][0];
            sF[r * SF_STR + c + 1]   = acc[nt][1];
            sF[(r + 8) * SF_STR + c]     = acc[nt][2];
            sF[(r + 8) * SF_STR + c + 1] = acc[nt][3];
        }
    }
    gbar(g);

    // scores0: ((e*4+h)*4+qi)*16+s, e<4
#pragma unroll 1
    for (int it = 0; it < 4; it++) {
        int idx = tl + it * 256;
        int s = idx & 15, qi = (idx >> 4) & 3, h = (idx >> 6) & 3, e = idx >> 8;
        const float4* qv = (const float4*)&sIq[qi * 128 + h * 32];
        const float4* kv = (const float4*)&sF[(e * 16 + s) * SF_STR + h * 32];
        float dot = sIqb[qi * 4 + h];
#pragma unroll
        for (int d4 = 0; d4 < 8; d4++) {
            float4 q = qv[d4], k = kv[d4];
            dot += q.x * k.x + q.y * k.y + q.z * k.z + q.w * k.w;
        }
        sScr[idx] = dot * SCALE_INV;
    }

    // ===== V0 gemm (compute overlaps scores0 consumers in other warps) =====
    {
        float acc[8][4] = {};
        gemm64(xh, xl, WF + 1 * 8192, wl, lane, acc);
        gbar(g);   // scores0 done reading K0 from sF
#pragma unroll
        for (int nt = 0; nt < 8; nt++) {
            int r = rg * 16 + l4, c = cg * 64 + nt * 8 + c2;
            sF[r * SF_STR + c]       = acc[nt][0] + sBias[c];
            sF[r * SF_STR + c + 1]   = acc[nt][1] + sBias[c + 1];
            sF[(r + 8) * SF_STR + c]     = acc[nt][2] + sBias[c];
            sF[(r + 8) * SF_STR + c + 1] = acc[nt][3] + sBias[c + 1];
        }
    }
    // softmax0: 64 rows of 16
    if (tl < 64) {
        float* p = &sScr[tl * 16];
        float mx = p[0];
#pragma unroll
        for (int i = 1; i < 16; i++) mx = fmaxf(mx, p[i]);
        float sum = 0.f;
#pragma unroll
        for (int i = 0; i < 16; i++) { float ex = expf(p[i] - mx); p[i] = ex; sum += ex; }
        float inv = 1.f / sum;
#pragma unroll
        for (int i = 0; i < 16; i++) p[i] *= inv;
    }
    gbar(g);

    // O0 = Iq + A@V0f -> sSm (16 rows)
#pragma unroll 1
    for (int it = 0; it < 8; it++) {
        int idx = tl + it * 256;
        int d = idx & 127, row = idx >> 7;     // row 0..15
        int qi = row & 3, e = row >> 2, h = d >> 5;
        float o = sIq[qi * 128 + d];
        const float* A = &sScr[((e * 4 + h) * 4 + qi) * 16];
        const float* vv = &sF[(e * 16) * SF_STR + d];
#pragma unroll
        for (int s = 0; s < 16; s++) o += A[s] * vv[s * SF_STR];
        sSm[row * SF_STR + d] = o;
    }
    gbar(g);

    // ===== Q1 gemm -> sF (+bq1) =====
    {
        float acc[8][4] = {};
        gemm64(xh, xl, WF + 2 * 8192, wl, lane, acc);
        gbar(g);   // O0 done reading V0f from sF
#pragma unroll
        for (int nt = 0; nt < 8; nt++) {
            int r = rg * 16 + l4, c = cg * 64 + nt * 8 + c2;
            sF[r * SF_STR + c]       = acc[nt][0] + sBias[2 * 128 + c];
            sF[r * SF_STR + c + 1]   = acc[nt][1] + sBias[2 * 128 + c + 1];
            sF[(r + 8) * SF_STR + c]     = acc[nt][2] + sBias[2 * 128 + c];
            sF[(r + 8) * SF_STR + c + 1] = acc[nt][3] + sBias[2 * 128 + c + 1];
        }
    }
    // O0 -> X image rows 0..15 (X dead: all 3 big gemms issued before last bar)
#pragma unroll 1
    for (int it = 0; it < 4; it++) {
        int i = tl + it * 256;       // 1024 pairs
        int r = i >> 6, c = (i & 63) * 2;
        img_st2(gm, r, c, sSm[r * SF_STR + c], sSm[r * SF_STR + c + 1]);
    }
    gbar(g);

    // ===== T0 = O0@Wo0 ; Hset = O0 + relu(T0+bo0) -> image rows 0..15 =====
    {
        float acc[2][4] = {};
        gemm16(xh, xl, WF + 3 * 8192, wl, lane, acc);
        gbar(g);   // all warps done reading O0 image
#pragma unroll
        for (int nt = 0; nt < 2; nt++) {
            int c = wl * 16 + nt * 8 + c2;
            float v0 = sSm[l4 * SF_STR + c]     + fmaxf(acc[nt][0] + sBias[128 + c], 0.f);
            float v1 = sSm[l4 * SF_STR + c + 1] + fmaxf(acc[nt][1] + sBias[128 + c + 1], 0.f);
            img_st2(gm, l4, c, v0, v1);
            float w0 = sSm[(l4 + 8) * SF_STR + c]     + fmaxf(acc[nt][2] + sBias[128 + c], 0.f);
            float w1 = sSm[(l4 + 8) * SF_STR + c + 1] + fmaxf(acc[nt][3] + sBias[128 + c + 1], 0.f);
            img_st2(gm, l4 + 8, c, w0, w1);
        }
    }
    gbar(g);

    // ===== K1 = Hset@Wk1 + bk1 -> sSm =====
    {
        float acc[2][4] = {};
        gemm16(xh, xl, WF + 4 * 8192, wl, lane, acc);
#pragma unroll
        for (int nt = 0; nt < 2; nt++) {
            int c = wl * 16 + nt * 8 + c2;
            sSm[l4 * SF_STR + c]       = acc[nt][0] + sBias[3 * 128 + c];
            sSm[l4 * SF_STR + c + 1]   = acc[nt][1] + sBias[3 * 128 + c + 1];
            sSm[(l4 + 8) * SF_STR + c]     = acc[nt][2] + sBias[3 * 128 + c];
            sSm[(l4 + 8) * SF_STR + c + 1] = acc[nt][3] + sBias[3 * 128 + c + 1];
        }
    }
    // ===== V1 = Hset@Wv1 + bv1 -> sV1f (XH rows 16.. dead) =====
    {
        float acc[2][4] = {};
        gemm16(xh, xl, WF + 5 * 8192, wl, lane, acc);
#pragma unroll
        for (int nt = 0; nt < 2; nt++) {
            int c = wl * 16 + nt * 8 + c2;
            sV1f[l4 * 128 + c]       = acc[nt][0] + sBias[4 * 128 + c];
            sV1f[l4 * 128 + c + 1]   = acc[nt][1] + sBias[4 * 128 + c + 1];
            sV1f[(l4 + 8) * 128 + c]     = acc[nt][2] + sBias[4 * 128 + c];
            sV1f[(l4 + 8) * 128 + c + 1] = acc[nt][3] + sBias[4 * 128 + c + 1];
        }
    }
    gbar(g);

    // scores1: ((e*4+h)*16+q)*4+k
#pragma unroll 1
    for (int it = 0; it < 4; it++) {
        int idx = tl + it * 256;
        int k = idx & 3, q = (idx >> 2) & 15, h = (idx >> 6) & 3, e = idx >> 8;
        const float4* qv = (const float4*)&sF[(e * 16 + q) * SF_STR + h * 32];
        const float4* kv = (const float4*)&sSm[(e * 4 + k) * SF_STR + h * 32];
        float dot = 0.f;
#pragma unroll
        for (int d4 = 0; d4 < 8; d4++) {
            float4 qq = qv[d4], kk = kv[d4];
            dot += qq.x * kk.x + qq.y * kk.y + qq.z * kk.z + qq.w * kk.w;
        }
        sScr[idx] = dot * SCALE_INV;
    }
    gbar(g);
    // softmax1: 256 rows of 4
    {
        float* p = &sScr[tl * 4];
        float mx = fmaxf(fmaxf(p[0], p[1]), fmaxf(p[2], p[3]));
        float e0 = expf(p[0] - mx), e1 = expf(p[1] - mx), e2 = expf(p[2] - mx), e3 = expf(p[3] - mx);
        float inv = 1.f / (e0 + e1 + e2 + e3);
        p[0] = e0 * inv; p[1] = e1 * inv; p[2] = e2 * inv; p[3] = e3 * inv;
    }
    gbar(g);

    // O = Q1f + A1@V1f, in place in sF
#pragma unroll 1
    for (int it = 0; it < 32; it++) {
        int idx = tl + it * 256;
        int d = idx & 127, row = idx >> 7;     // row 0..63
        int q = row & 15, e = row >> 4, h = d >> 5;
        float o = sF[row * SF_STR + d];
        const float* A = &sScr[((e * 4 + h) * 16 + q) * 4];
        const float* vv = &sV1f[(e * 4) * 128 + d];
#pragma unroll
        for (int k = 0; k < 4; k++) o += A[k] * vv[k * 128];
        sF[row * SF_STR + d] = o;
    }
    gbar(g);

    // O -> X image rows 0..63 (V1f dead)
#pragma unroll 1
    for (int it = 0; it < 16; it++) {
        int i = tl + it * 256;       // 4096 pairs
        int r = i >> 6, c = (i & 63) * 2;
        img_st2(gm, r, c, sF[r * SF_STR + c], sF[r * SF_STR + c + 1]);
    }
    gbar(g);

    // ===== T1 = O@Wo1 ; final = O + relu(T1+bo1) -> sF in place =====
    {
        float acc[8][4] = {};
        gemm64(xh, xl, WF + 6 * 8192, wl, lane, acc);
        gbar(g);
#pragma unroll
        for (int nt = 0; nt < 8; nt++) {
            int r = rg * 16 + l4, c = cg * 64 + nt * 8 + c2;
            sF[r * SF_STR + c]       += fmaxf(acc[nt][0] + sBias[5 * 128 + c], 0.f);
            sF[r * SF_STR + c + 1]   += fmaxf(acc[nt][1] + sBias[5 * 128 + c + 1], 0.f);
            sF[(r + 8) * SF_STR + c]     += fmaxf(acc[nt][2] + sBias[5 * 128 + c], 0.f);
            sF[(r + 8) * SF_STR + c + 1] += fmaxf(acc[nt][3] + sBias[5 * 128 + c + 1], 0.f);
        }
    }
    gbar(g);

    // logits = final @ Wout + bout  (384 items per group)
#pragma unroll 1
    for (int it = 0; it < 2; it++) {
        int idx = tl + it * 256;
        if (idx < 384) {
            int c = idx % C_CLS, r = idx / C_CLS;
            float acc = sWo[768 + c];
            const float4* xr = (const float4*)&sF[r * SF_STR];
#pragma unroll
            for (int k4 = 0; k4 < 32; k4++) {
                float4 x = xr[k4];
                acc += x.x * sWo[(k4 * 4 + 0) * C_CLS + c]
                     + x.y * sWo[(k4 * 4 + 1) * C_CLS + c]
                     + x.z * sWo[(k4 * 4 + 2) * C_CLS + c]
                     + x.w * sWo[(k4 * 4 + 3) * C_CLS + c];
            }
            long long off = (long long)(rowbase + r) * C_CLS + c;
            if (off < out_capacity) out[off] = acc;
        }
    }
    long long lab_base = (long long)E_EDGES * S_MEM * C_CLS;
    if (out_capacity >= lab_base + (long long)E_EDGES * S_MEM && tl < 64) {
        out[lab_base + rowbase + tl] = (float)labels[rowbase + tl];
    }
}

extern "C" void kernel_launch(void* const* d_in, const int* in_sizes, int n_in,
                              void* d_out, int out_size) {
    const float* Ws[8] = {0,0,0,0,0,0,0,0};
    const float* Bs[8] = {0,0,0,0,0,0,0,0};
    const float* vfeat = 0; const float* Iin = 0;
    const float* Wout = 0;  const float* bout = 0;
    const int* member_idx = 0; const int* labels = 0;
    int wi = 0, bi = 0, n_nodes = 500000;
    for (int i = 0; i < n_in; i++) {
        int sz = in_sizes[i];
        if (sz == 500000 * 128)      { vfeat = (const float*)d_in[i]; n_nodes = sz / D_DIM; }
        else if (sz == E_EDGES * S_MEM) {
            if (!member_idx) member_idx = (const int*)d_in[i];
            else if (!labels) labels = (const int*)d_in[i];
        }
        else if (sz == M_IND * D_DIM) Iin = (const float*)d_in[i];
        else if (sz == D_DIM * C_CLS) Wout = (const float*)d_in[i];
        else if (sz == C_CLS)         bout = (const float*)d_in[i];
        else if (sz == D_DIM * D_DIM) { if (wi < 8) Ws[wi++] = (const float*)d_in[i]; }
        else if (sz == D_DIM)         { if (bi < 8) Bs[bi++] = (const float*)d_in[i]; }
    }
    if (!vfeat || !member_idx || !labels || !Iin || !Wout || !bout || wi != 8 || bi != 8) {
        vfeat = (const float*)d_in[0]; member_idx = (const int*)d_in[1];
        labels = (const int*)d_in[2];  Iin = (const float*)d_in[3];
        Wout = (const float*)d_in[4];  bout = (const float*)d_in[5];
        for (int j = 0; j < 8; j++) { Ws[j] = (const float*)d_in[6 + 2 * j]; Bs[j] = (const float*)d_in[7 + 2 * j]; }
        n_nodes = in_sizes[0] / D_DIM;
    }
    const float *Wq0 = Ws[0], *Wk0 = Ws[1], *Wv0 = Ws[2], *Wo0 = Ws[3];
    const float *Wq1 = Ws[4], *Wk1 = Ws[5], *Wv1 = Ws[6], *Wo1 = Ws[7];
    const float *bq0 = Bs[0], *bk0 = Bs[1], *bv0 = Bs[2], *bo0 = Bs[3];
    const float *bq1 = Bs[4], *bk1 = Bs[5], *bv1 = Bs[6], *bo1 = Bs[7];

    cudaFuncSetAttribute(whatsnet_mma2, cudaFuncAttributeMaxDynamicSharedMemorySize, SMEM_TOTAL);

    iq_kernel<<<2, 256>>>(Iin, Wq0, bq0);
    iqb_kernel<<<1, 32>>>(bk0);
    wconv_kernel<<<7, 256>>>(Wk0, Wv0, Wq1, Wo0, Wk1, Wv1, Wo1);

    whatsnet_mma2<<<E_EDGES / 8, NTH, SMEM_TOTAL>>>(
        vfeat, member_idx, labels, Wout, bout,
        bv0, bo0, bq1, bk1, bv1, bo1,
        (float*)d_out, n_nodes, (long long)out_size);
}

// round 10
// speedup vs baseline: 1.3636x; 1.3636x over previous
#include <cuda_runtime.h>
#include <cuda_bf16.h>
#include <math.h>
#include <stdint.h>

#define E_EDGES 100000
#define S_MEM   16
#define D_DIM   128
#define C_CLS   6
#define M_IND   4
#define ROWS    128
#define NTHREADS 256
#define SCALE_INV 0.08838834764831845f

// SMEM byte offsets
#define OFF_XH  0
#define OFF_XL  32768
#define OFF_WH  65536
#define OFF_WL  98304
#define OFF_SF  131072                 // f32 [128][132]
#define SF_STR  132
#define OFF_SSM (OFF_SF + 128*SF_STR*4)    // f32 [32][132]
#define OFF_BIAS (OFF_SSM + 32*SF_STR*4)   // f32 [6][128]
#define OFF_IQ  (OFF_BIAS + 6*128*4)       // f32 [512]
#define OFF_IQB (OFF_IQ + 2048)            // f32 [16]
#define OFF_WOUT (OFF_IQB + 64)            // f32 [776]
#define OFF_SCR (OFF_WOUT + 3104)          // f32 [2048]
#define SMEM_TOTAL (OFF_SCR + 8192)        // 232032 <= 232448

__device__ __align__(16) float g_Iq[M_IND * D_DIM];
__device__ __align__(16) float g_Iqb[16];
// weight images, [n][k] row-major bf16 with 16B-chunk XOR swizzle
// widx: 0=Wk0 1=Wv0 2=Wq1 3=Wo0 4=Wk1 5=Wv1 6=Wo1
__device__ __align__(16) __nv_bfloat16 g_WH[7][16384];
__device__ __align__(16) __nv_bfloat16 g_WL[7][16384];

__host__ __device__ __forceinline__ int imgoff(int r, int c) {
    return r * 256 + (((c >> 3) ^ (r & 7)) << 4) + ((c & 7) << 1);
}

__device__ __forceinline__ uint32_t cvta_s(const void* p) {
    uint32_t a;
    asm("{ .reg .u64 t; cvta.to.shared.u64 t, %1; cvt.u32.u64 %0, t; }" : "=r"(a) : "l"(p));
    return a;
}
__device__ __forceinline__ void ldsm4(uint32_t* a, uint32_t addr) {
    asm volatile("ldmatrix.sync.aligned.m8n8.x4.shared.b16 {%0,%1,%2,%3}, [%4];"
        : "=r"(a[0]), "=r"(a[1]), "=r"(a[2]), "=r"(a[3]) : "r"(addr));
}
__device__ __forceinline__ void mma16816(float* c, const uint32_t* a, uint32_t b0, uint32_t b1) {
    asm volatile("mma.sync.aligned.m16n8k16.row.col.f32.bf16.bf16.f32 "
        "{%0,%1,%2,%3}, {%4,%5,%6,%7}, {%8,%9}, {%0,%1,%2,%3};"
        : "+f"(c[0]), "+f"(c[1]), "+f"(c[2]), "+f"(c[3])
        : "r"(a[0]), "r"(a[1]), "r"(a[2]), "r"(a[3]), "r"(b0), "r"(b1));
}
__device__ __forceinline__ void cp16(uint32_t dst, const void* src) {
    asm volatile("cp.async.cg.shared.global [%0], [%1], 16;" :: "r"(dst), "l"(src) : "memory");
}
__device__ __forceinline__ void cp_commit() { asm volatile("cp.async.commit_group;" ::: "memory"); }
__device__ __forceinline__ void cp_wait()   { asm volatile("cp.async.wait_group 0;" ::: "memory"); }

__device__ __forceinline__ void img_st(char* sm, int r, int c, float v) {
    int i = imgoff(r, c);
    __nv_bfloat16 h = __float2bfloat16(v);
    *(__nv_bfloat16*)(sm + OFF_XH + i) = h;
    *(__nv_bfloat16*)(sm + OFF_XL + i) = __float2bfloat16(v - __bfloat162float(h));
}
__device__ __forceinline__ void img_st2(char* sm, int r, int c, float v0, float v1) {
    int i = imgoff(r, c);
    __nv_bfloat162 h, l;
    h.x = __float2bfloat16(v0); h.y = __float2bfloat16(v1);
    l.x = __float2bfloat16(v0 - __bfloat162float(h.x));
    l.y = __float2bfloat16(v1 - __bfloat162float(h.y));
    *(__nv_bfloat162*)(sm + OFF_XH + i) = h;
    *(__nv_bfloat162*)(sm + OFF_XL + i) = l;
}

// ---------------- prologs ----------------
__global__ void iq_kernel(const float* __restrict__ I, const float* __restrict__ Wq,
                          const float* __restrict__ bq) {
    int idx = blockIdx.x * blockDim.x + threadIdx.x;
    if (idx >= M_IND * D_DIM) return;
    int qi = idx / D_DIM, d = idx % D_DIM;
    float acc = bq[d];
    for (int k = 0; k < D_DIM; k++) acc += I[qi * D_DIM + k] * Wq[k * D_DIM + d];
    g_Iq[idx] = acc;
}
__global__ void iqb_kernel(const float* __restrict__ bk0) {
    int t = threadIdx.x;
    if (t < 16) {
        int qi = t >> 2, h = t & 3;
        float s = 0.f;
        for (int j = 0; j < 32; j++) s += g_Iq[qi * 128 + h * 32 + j] * bk0[h * 32 + j];
        g_Iqb[t] = s;
    }
}
__global__ void wconv_kernel(const float* W0, const float* W1, const float* W2, const float* W3,
                             const float* W4, const float* W5, const float* W6) {
    const float* W;
    int m = blockIdx.x;
    switch (m) { case 0: W = W0; break; case 1: W = W1; break; case 2: W = W2; break;
                 case 3: W = W3; break; case 4: W = W4; break; case 5: W = W5; break;
                 default: W = W6; }
    for (int i = threadIdx.x; i < 16384; i += blockDim.x) {
        int n = i >> 7, k = i & 127;
        float w = W[k * 128 + n];          // B[n][k] = W[k][n]
        __nv_bfloat16 h = __float2bfloat16(w);
        int idx = n * 128 + (((k >> 3) ^ (n & 7)) << 3) + (k & 7);
        g_WH[m][idx] = h;
        g_WL[m][idx] = __float2bfloat16(w - __bfloat162float(h));
    }
}

// issue async stage of weight images (no barrier; overlap with scalar work)
__device__ __forceinline__ void lw_issue(char* sm, uint32_t sb, int widx, int tid) {
    const char* gh = (const char*)g_WH[widx];
    const char* gl = (const char*)g_WL[widx];
    uint32_t dh = sb + OFF_WH, dl = sb + OFF_WL;
#pragma unroll
    for (int i = 0; i < 8; i++) {
        int off = (tid + i * 256) * 16;
        cp16(dh + off, gh + off);
        cp16(dl + off, gl + off);
    }
    cp_commit();
}

// 128x128x128 GEMM, 3-pass bf16 split, ldsm4 for A and B
__device__ __forceinline__ void gemm128(uint32_t xh, uint32_t xl, uint32_t wh, uint32_t wl,
                                        int wid, int lane, float acc[2][8][4]) {
    const int rg = wid >> 1, cg = wid & 1;
    const int lr = lane & 15, lh = lane >> 4;
    const int bn = (lane & 7) + ((lane >> 4) << 3);   // row within 16-row pair
    const int bh2 = (lane >> 3) & 1;                  // k-half select
#pragma unroll
    for (int ks = 0; ks < 8; ks++) {
        uint32_t ah[2][4], al[2][4];
#pragma unroll
        for (int rt = 0; rt < 2; rt++) {
            int r = rg * 32 + rt * 16 + lr;
            uint32_t off = (uint32_t)(r * 256 + (((ks * 2 + lh) ^ (r & 7)) << 4));
            ldsm4(ah[rt], xh + off);
            ldsm4(al[rt], xl + off);
        }
#pragma unroll
        for (int ntp = 0; ntp < 4; ntp++) {
            int n = cg * 64 + ntp * 16 + bn;
            uint32_t boff = (uint32_t)(n * 256 + (((ks * 2 + bh2) ^ (n & 7)) << 4));
            uint32_t bh[4], bl[4];
            ldsm4(bh, wh + boff);
            ldsm4(bl, wl + boff);
#pragma unroll
            for (int rt = 0; rt < 2; rt++) {
                mma16816(acc[rt][2 * ntp],     ah[rt], bh[0], bh[1]);
                mma16816(acc[rt][2 * ntp],     al[rt], bh[0], bh[1]);
                mma16816(acc[rt][2 * ntp],     ah[rt], bl[0], bl[1]);
                mma16816(acc[rt][2 * ntp + 1], ah[rt], bh[2], bh[3]);
                mma16816(acc[rt][2 * ntp + 1], al[rt], bh[2], bh[3]);
                mma16816(acc[rt][2 * ntp + 1], ah[rt], bl[2], bl[3]);
            }
        }
    }
}

// 32x128x128 GEMM; warp = (rowtile wid>>2, colgroup wid&3)
__device__ __forceinline__ void gemm32(uint32_t xh, uint32_t xl, uint32_t wh, uint32_t wl,
                                       int wid, int lane, float acc[4][4]) {
    const int rt = wid >> 2, cg = wid & 3;
    const int lr = lane & 15, lh = lane >> 4;
    const int bn = (lane & 7) + ((lane >> 4) << 3);
    const int bh2 = (lane >> 3) & 1;
#pragma unroll
    for (int ks = 0; ks < 8; ks++) {
        uint32_t ah[4], al[4];
        int r = rt * 16 + lr;
        uint32_t off = (uint32_t)(r * 256 + (((ks * 2 + lh) ^ (r & 7)) << 4));
        ldsm4(ah, xh + off);
        ldsm4(al, xl + off);
#pragma unroll
        for (int ntp = 0; ntp < 2; ntp++) {
            int n = cg * 32 + ntp * 16 + bn;
            uint32_t boff = (uint32_t)(n * 256 + (((ks * 2 + bh2) ^ (n & 7)) << 4));
            uint32_t bh[4], bl[4];
            ldsm4(bh, wh + boff);
            ldsm4(bl, wl + boff);
            mma16816(acc[2 * ntp],     ah, bh[0], bh[1]);
            mma16816(acc[2 * ntp],     al, bh[0], bh[1]);
            mma16816(acc[2 * ntp],     ah, bl[0], bl[1]);
            mma16816(acc[2 * ntp + 1], ah, bh[2], bh[3]);
            mma16816(acc[2 * ntp + 1], al, bh[2], bh[3]);
            mma16816(acc[2 * ntp + 1], ah, bl[2], bl[3]);
        }
    }
}

extern "C" __global__ void __launch_bounds__(NTHREADS, 1)
whatsnet_mma(const float* __restrict__ vfeat, const int* __restrict__ member_idx,
             const int* __restrict__ labels,
             const float* __restrict__ Wout, const float* __restrict__ bout,
             const float* __restrict__ bv0, const float* __restrict__ bo0,
             const float* __restrict__ bq1, const float* __restrict__ bk1,
             const float* __restrict__ bv1, const float* __restrict__ bo1,
             float* __restrict__ out, int n_nodes, long long out_capacity)
{
    extern __shared__ char sm[];
    const int tid = threadIdx.x;
    const int wid = tid >> 5, lane = tid & 31;
    const int rowbase = blockIdx.x * ROWS;
    const uint32_t sb = cvta_s(sm);
    const uint32_t xh = sb + OFF_XH, xl = sb + OFF_XL;
    const uint32_t wh = sb + OFF_WH, wl = sb + OFF_WL;

    float* sF   = (float*)(sm + OFF_SF);
    float* sSm  = (float*)(sm + OFF_SSM);
    float* sBias= (float*)(sm + OFF_BIAS);
    float* sIq  = (float*)(sm + OFF_IQ);
    float* sIqb = (float*)(sm + OFF_IQB);
    float* sWo  = (float*)(sm + OFF_WOUT);
    float* sScr = (float*)(sm + OFF_SCR);
    float* sV1f = (float*)(sm + OFF_XH + 4096);   // 32x128 f32 scratch (X rows 16..47, dead then)

    // constants
    if (tid < 128) {
        sBias[0 * 128 + tid] = bv0[tid];
        sBias[1 * 128 + tid] = bo0[tid];
        sBias[2 * 128 + tid] = bq1[tid];
        sBias[3 * 128 + tid] = bk1[tid];
        sBias[4 * 128 + tid] = bv1[tid];
        sBias[5 * 128 + tid] = bo1[tid];
    }
    for (int i = tid; i < 512; i += NTHREADS) sIq[i] = g_Iq[i];
    if (tid < 16) sIqb[tid] = g_Iqb[tid];
    for (int i = tid; i < 768; i += NTHREADS) sWo[i] = Wout[i];
    if (tid < 6) sWo[768 + tid] = bout[tid];

    // stage W0 while gathering
    lw_issue(sm, sb, 0, tid);

    // gather -> X images
    for (int r = wid; r < ROWS; r += 8) {
        int n = member_idx[rowbase + r];
        if (n < 0) n = 0;
        if (n >= n_nodes) n = n_nodes - 1;
        const float* src = vfeat + (size_t)n * D_DIM;
#pragma unroll
        for (int k = 0; k < 4; k++) {
            int c = lane + k * 32;
            img_st(sm, r, c, src[c]);
        }
    }
    cp_wait();
    __syncthreads();

    const int l4 = lane >> 2, c2 = (lane & 3) * 2;
    const int rg = wid >> 1, cg = wid & 1;

    float acc[2][8][4];
    float acc32[4][4];

    // ===== K0 = X@Wk0 =====
#pragma unroll
    for (int i = 0; i < 2; i++)
#pragma unroll
        for (int j = 0; j < 8; j++)
#pragma unroll
            for (int q = 0; q < 4; q++) acc[i][j][q] = 0.f;
    gemm128(xh, xl, wh, wl, wid, lane, acc);
    __syncthreads();                       // W0 reads done
    lw_issue(sm, sb, 1, tid);              // stage Wv0 (overlaps scores0)
#pragma unroll
    for (int rt = 0; rt < 2; rt++)
#pragma unroll
        for (int nt = 0; nt < 8; nt++) {
            int r = rg * 32 + rt * 16 + l4, c = cg * 64 + nt * 8 + c2;
            sF[r * SF_STR + c]       = acc[rt][nt][0];
            sF[r * SF_STR + c + 1]   = acc[rt][nt][1];
            sF[(r + 8) * SF_STR + c]     = acc[rt][nt][2];
            sF[(r + 8) * SF_STR + c + 1] = acc[rt][nt][3];
        }
    __syncthreads();

    // scores0: ((e*4+h)*4+qi)*16+s
#pragma unroll 1
    for (int it = 0; it < 8; it++) {
        int idx = tid + it * 256;
        int s = idx & 15, qi = (idx >> 4) & 3, h = (idx >> 6) & 3, e = idx >> 8;
        const float4* qv = (const float4*)&sIq[qi * 128 + h * 32];
        const float4* kv = (const float4*)&sF[(e * 16 + s) * SF_STR + h * 32];
        float dot = sIqb[qi * 4 + h];
#pragma unroll
        for (int d4 = 0; d4 < 8; d4++) {
            float4 q = qv[d4], k = kv[d4];
            dot += q.x * k.x + q.y * k.y + q.z * k.z + q.w * k.w;
        }
        sScr[idx] = dot * SCALE_INV;
    }
    cp_wait();
    __syncthreads();                       // scores0 done reading sF; W1 visible

    // ===== V0 = X@Wv0 + bv0 -> sF =====
#pragma unroll
    for (int i = 0; i < 2; i++)
#pragma unroll
        for (int j = 0; j < 8; j++)
#pragma unroll
            for (int q = 0; q < 4; q++) acc[i][j][q] = 0.f;
    gemm128(xh, xl, wh, wl, wid, lane, acc);
    __syncthreads();                       // W1 reads done
    lw_issue(sm, sb, 2, tid);              // stage Wq1 (overlaps softmax0 + O0)
#pragma unroll
    for (int rt = 0; rt < 2; rt++)
#pragma unroll
        for (int nt = 0; nt < 8; nt++) {
            int r = rg * 32 + rt * 16 + l4, c = cg * 64 + nt * 8 + c2;
            sF[r * SF_STR + c]       = acc[rt][nt][0] + sBias[c];
            sF[r * SF_STR + c + 1]   = acc[rt][nt][1] + sBias[c + 1];
            sF[(r + 8) * SF_STR + c]     = acc[rt][nt][2] + sBias[c];
            sF[(r + 8) * SF_STR + c + 1] = acc[rt][nt][3] + sBias[c + 1];
        }
    // softmax0 (sScr, independent of sF stores above)
    if (tid < 128) {
        float* p = &sScr[tid * 16];
        float mx = p[0];
#pragma unroll
        for (int i = 1; i < 16; i++) mx = fmaxf(mx, p[i]);
        float sum = 0.f;
#pragma unroll
        for (int i = 0; i < 16; i++) { float ex = expf(p[i] - mx); p[i] = ex; sum += ex; }
        float inv = 1.f / sum;
#pragma unroll
        for (int i = 0; i < 16; i++) p[i] *= inv;
    }
    __syncthreads();

    // O0 = Iq + A @ V0f -> sSm (32 rows)
#pragma unroll 1
    for (int it = 0; it < 16; it++) {
        int idx = tid + it * 256;
        int d = idx & 127, row = idx >> 7;
        int qi = row & 3, e = row >> 2, h = d >> 5;
        float o = sIq[qi * 128 + d];
        const float* A = &sScr[((e * 4 + h) * 4 + qi) * 16];
        const float* vv = &sF[(e * 16) * SF_STR + d];
#pragma unroll
        for (int s = 0; s < 16; s++) o += A[s] * vv[s * SF_STR];
        sSm[row * SF_STR + d] = o;
    }
    cp_wait();
    __syncthreads();                       // W2 visible

    // ===== Q1 = X@Wq1 + bq1 -> sF =====
#pragma unroll
    for (int i = 0; i < 2; i++)
#pragma unroll
        for (int j = 0; j < 8; j++)
#pragma unroll
            for (int q = 0; q < 4; q++) acc[i][j][q] = 0.f;
    gemm128(xh, xl, wh, wl, wid, lane, acc);
    __syncthreads();                       // W2 + X reads done (X dead now)
    lw_issue(sm, sb, 3, tid);              // stage Wo0 (overlaps Q1 store + O0 img)
#pragma unroll
    for (int rt = 0; rt < 2; rt++)
#pragma unroll
        for (int nt = 0; nt < 8; nt++) {
            int r = rg * 32 + rt * 16 + l4, c = cg * 64 + nt * 8 + c2;
            sF[r * SF_STR + c]       = acc[rt][nt][0] + sBias[2 * 128 + c];
            sF[r * SF_STR + c + 1]   = acc[rt][nt][1] + sBias[2 * 128 + c + 1];
            sF[(r + 8) * SF_STR + c]     = acc[rt][nt][2] + sBias[2 * 128 + c];
            sF[(r + 8) * SF_STR + c + 1] = acc[rt][nt][3] + sBias[2 * 128 + c + 1];
        }
    // O0 -> X image rows 0..31
    for (int i = tid; i < 2048; i += NTHREADS) {
        int r = i >> 6, c = (i & 63) * 2;
        img_st2(sm, r, c, sSm[r * SF_STR + c], sSm[r * SF_STR + c + 1]);
    }
    cp_wait();
    __syncthreads();                       // O0 image + W3 visible

    // ===== T0 = O0@Wo0 ; Hset = O0 + relu(T0+bo0) -> image rows 0..31 =====
#pragma unroll
    for (int j = 0; j < 4; j++)
#pragma unroll
        for (int q = 0; q < 4; q++) acc32[j][q] = 0.f;
    gemm32(xh, xl, wh, wl, wid, lane, acc32);
    __syncthreads();                       // all O0-image reads done; W3 done
    lw_issue(sm, sb, 4, tid);              // stage Wk1 (overlaps Hset write)
    {
        int rt = wid >> 2, cgs = wid & 3;
        int r = rt * 16 + l4;
#pragma unroll
        for (int nt = 0; nt < 4; nt++) {
            int c = cgs * 32 + nt * 8 + c2;
            float v0 = sSm[r * SF_STR + c]     + fmaxf(acc32[nt][0] + sBias[128 + c], 0.f);
            float v1 = sSm[r * SF_STR + c + 1] + fmaxf(acc32[nt][1] + sBias[128 + c + 1], 0.f);
            img_st2(sm, r, c, v0, v1);
            float w0 = sSm[(r + 8) * SF_STR + c]     + fmaxf(acc32[nt][2] + sBias[128 + c], 0.f);
            float w1 = sSm[(r + 8) * SF_STR + c + 1] + fmaxf(acc32[nt][3] + sBias[128 + c + 1], 0.f);
            img_st2(sm, r + 8, c, w0, w1);
        }
    }
    cp_wait();
    __syncthreads();                       // Hset image + W4 visible

    // ===== K1 = Hset@Wk1 + bk1 -> sSm =====
#pragma unroll
    for (int j = 0; j < 4; j++)
#pragma unroll
        for (int q = 0; q < 4; q++) acc32[j][q] = 0.f;
    gemm32(xh, xl, wh, wl, wid, lane, acc32);
    __syncthreads();                       // W4 reads done
    lw_issue(sm, sb, 5, tid);              // stage Wv1
    {
        int rt = wid >> 2, cgs = wid & 3;
        int r = rt * 16 + l4;
#pragma unroll
        for (int nt = 0; nt < 4; nt++) {
            int c = cgs * 32 + nt * 8 + c2;
            sSm[r * SF_STR + c]       = acc32[nt][0] + sBias[3 * 128 + c];
            sSm[r * SF_STR + c + 1]   = acc32[nt][1] + sBias[3 * 128 + c + 1];
            sSm[(r + 8) * SF_STR + c]     = acc32[nt][2] + sBias[3 * 128 + c];
            sSm[(r + 8) * SF_STR + c + 1] = acc32[nt][3] + sBias[3 * 128 + c + 1];
        }
    }
    cp_wait();
    __syncthreads();                       // W5 visible

    // ===== V1 = Hset@Wv1 + bv1 -> sV1f =====
#pragma unroll
    for (int j = 0; j < 4; j++)
#pragma unroll
        for (int q = 0; q < 4; q++) acc32[j][q] = 0.f;
    gemm32(xh, xl, wh, wl, wid, lane, acc32);
    __syncthreads();                       // image reads done (Hset dead); W5 done
    lw_issue(sm, sb, 6, tid);              // stage Wo1 (overlaps attn1)
    {
        int rt = wid >> 2, cgs = wid & 3;
        int r = rt * 16 + l4;
#pragma unroll
        for (int nt = 0; nt < 4; nt++) {
            int c = cgs * 32 + nt * 8 + c2;
            sV1f[r * 128 + c]       = acc32[nt][0] + sBias[4 * 128 + c];
            sV1f[r * 128 + c + 1]   = acc32[nt][1] + sBias[4 * 128 + c + 1];
            sV1f[(r + 8) * 128 + c]     = acc32[nt][2] + sBias[4 * 128 + c];
            sV1f[(r + 8) * 128 + c + 1] = acc32[nt][3] + sBias[4 * 128 + c + 1];
        }
    }
    __syncthreads();

    // scores1: ((e*4+h)*16+q)*4+k
#pragma unroll 1
    for (int it = 0; it < 8; it++) {
        int idx = tid + it * 256;
        int k = idx & 3, q = (idx >> 2) & 15, h = (idx >> 6) & 3, e = idx >> 8;
        const float4* qv = (const float4*)&sF[(e * 16 + q) * SF_STR + h * 32];
        const float4* kv = (const float4*)&sSm[(e * 4 + k) * SF_STR + h * 32];
        float dot = 0.f;
#pragma unroll
        for (int d4 = 0; d4 < 8; d4++) {
            float4 qq = qv[d4], kk = kv[d4];
            dot += qq.x * kk.x + qq.y * kk.y + qq.z * kk.z + qq.w * kk.w;
        }
        sScr[idx] = dot * SCALE_INV;
    }
    __syncthreads();
    for (int rr = tid; rr < 512; rr += 256) {
        float* p = &sScr[rr * 4];
        float mx = fmaxf(fmaxf(p[0], p[1]), fmaxf(p[2], p[3]));
        float e0 = expf(p[0] - mx), e1 = expf(p[1] - mx), e2 = expf(p[2] - mx), e3 = expf(p[3] - mx);
        float inv = 1.f / (e0 + e1 + e2 + e3);
        p[0] = e0 * inv; p[1] = e1 * inv; p[2] = e2 * inv; p[3] = e3 * inv;
    }
    __syncthreads();

    // O = Q1 + A1@V1f, in place in sF
#pragma unroll 1
    for (int it = 0; it < 64; it++) {
        int idx = tid + it * 256;
        int d = idx & 127, row = idx >> 7;
        int q = row & 15, e = row >> 4, h = d >> 5;
        float o = sF[row * SF_STR + d];
        const float* A = &sScr[((e * 4 + h) * 16 + q) * 4];
        const float* vv = &sV1f[(e * 4) * 128 + d];
#pragma unroll
        for (int k = 0; k < 4; k++) o += A[k] * vv[k * 128];
        sF[row * SF_STR + d] = o;
    }
    __syncthreads();

    // O -> X images (full 128 rows; overwrites sV1f region, now dead)
    for (int i = tid; i < 8192; i += NTHREADS) {
        int r = i >> 6, c = (i & 63) * 2;
        img_st2(sm, r, c, sF[r * SF_STR + c], sF[r * SF_STR + c + 1]);
    }
    cp_wait();
    __syncthreads();                       // O image + W6 visible

    // ===== T1 = O@Wo1 ; final = O + relu(T1+bo1) -> sF in place =====
#pragma unroll
    for (int i = 0; i < 2; i++)
#pragma unroll
        for (int j = 0; j < 8; j++)
#pragma unroll
            for (int q = 0; q < 4; q++) acc[i][j][q] = 0.f;
    gemm128(xh, xl, wh, wl, wid, lane, acc);
#pragma unroll
    for (int rt = 0; rt < 2; rt++)
#pragma unroll
        for (int nt = 0; nt < 8; nt++) {
            int r = rg * 32 + rt * 16 + l4, c = cg * 64 + nt * 8 + c2;
            sF[r * SF_STR + c]       += fmaxf(acc[rt][nt][0] + sBias[5 * 128 + c], 0.f);
            sF[r * SF_STR + c + 1]   += fmaxf(acc[rt][nt][1] + sBias[5 * 128 + c + 1], 0.f);
            sF[(r + 8) * SF_STR + c]     += fmaxf(acc[rt][nt][2] + sBias[5 * 128 + c], 0.f);
            sF[(r + 8) * SF_STR + c + 1] += fmaxf(acc[rt][nt][3] + sBias[5 * 128 + c + 1], 0.f);
        }
    __syncthreads();

    // logits = final @ Wout + bout
#pragma unroll 1
    for (int it = 0; it < 3; it++) {
        int idx = tid + it * 256;
        int c = idx % C_CLS, r = idx / C_CLS;
        float a = sWo[768 + c];
        const float4* xr = (const float4*)&sF[r * SF_STR];
#pragma unroll
        for (int k4 = 0; k4 < 32; k4++) {
            float4 x = xr[k4];
            a += x.x * sWo[(k4 * 4 + 0) * C_CLS + c]
               + x.y * sWo[(k4 * 4 + 1) * C_CLS + c]
               + x.z * sWo[(k4 * 4 + 2) * C_CLS + c]
               + x.w * sWo[(k4 * 4 + 3) * C_CLS + c];
        }
        long long off = (long long)(rowbase + r) * C_CLS + c;
        if (off < out_capacity) out[off] = a;
    }
    long long lab_base = (long long)E_EDGES * S_MEM * C_CLS;
    if (out_capacity >= lab_base + (long long)E_EDGES * S_MEM) {
        for (int r = tid; r < ROWS; r += 256)
            out[lab_base + rowbase + r] = (float)labels[rowbase + r];
    }
}

extern "C" void kernel_launch(void* const* d_in, const int* in_sizes, int n_in,
                              void* d_out, int out_size) {
    const float* Ws[8] = {0,0,0,0,0,0,0,0};
    const float* Bs[8] = {0,0,0,0,0,0,0,0};
    const float* vfeat = 0; const float* Iin = 0;
    const float* Wout = 0;  const float* bout = 0;
    const int* member_idx = 0; const int* labels = 0;
    int wi = 0, bi = 0, n_nodes = 500000;
    for (int i = 0; i < n_in; i++) {
        int sz = in_sizes[i];
        if (sz == 500000 * 128)      { vfeat = (const float*)d_in[i]; n_nodes = sz / D_DIM; }
        else if (sz == E_EDGES * S_MEM) {
            if (!member_idx) member_idx = (const int*)d_in[i];
            else if (!labels) labels = (const int*)d_in[i];
        }
        else if (sz == M_IND * D_DIM) Iin = (const float*)d_in[i];
        else if (sz == D_DIM * C_CLS) Wout = (const float*)d_in[i];
        else if (sz == C_CLS)         bout = (const float*)d_in[i];
        else if (sz == D_DIM * D_DIM) { if (wi < 8) Ws[wi++] = (const float*)d_in[i]; }
        else if (sz == D_DIM)         { if (bi < 8) Bs[bi++] = (const float*)d_in[i]; }
    }
    if (!vfeat || !member_idx || !labels || !Iin || !Wout || !bout || wi != 8 || bi != 8) {
        vfeat = (const float*)d_in[0]; member_idx = (const int*)d_in[1];
        labels = (const int*)d_in[2];  Iin = (const float*)d_in[3];
        Wout = (const float*)d_in[4];  bout = (const float*)d_in[5];
        for (int j = 0; j < 8; j++) { Ws[j] = (const float*)d_in[6 + 2 * j]; Bs[j] = (const float*)d_in[7 + 2 * j]; }
        n_nodes = in_sizes[0] / D_DIM;
    }
    const float *Wq0 = Ws[0], *Wk0 = Ws[1], *Wv0 = Ws[2], *Wo0 = Ws[3];
    const float *Wq1 = Ws[4], *Wk1 = Ws[5], *Wv1 = Ws[6], *Wo1 = Ws[7];
    const float *bq0 = Bs[0], *bk0 = Bs[1], *bv0 = Bs[2], *bo0 = Bs[3];
    const float *bq1 = Bs[4], *bk1 = Bs[5], *bv1 = Bs[6], *bo1 = Bs[7];

    cudaFuncSetAttribute(whatsnet_mma, cudaFuncAttributeMaxDynamicSharedMemorySize, SMEM_TOTAL);

    iq_kernel<<<2, 256>>>(Iin, Wq0, bq0);
    iqb_kernel<<<1, 32>>>(bk0);
    wconv_kernel<<<7, 256>>>(Wk0, Wv0, Wq1, Wo0, Wk1, Wv1, Wo1);

    whatsnet_mma<<<E_EDGES * S_MEM / ROWS, NTHREADS, SMEM_TOTAL>>>(
        vfeat, member_idx, labels, Wout, bout,
        bv0, bo0, bq1, bk1, bv1, bo1,
        (float*)d_out, n_nodes, (long long)out_size);
}

// round 12
// speedup vs baseline: 1.5232x; 1.1170x over previous
#include <cuda_runtime.h>
#include <cuda_bf16.h>
#include <math.h>
#include <stdint.h>

#define E_EDGES 100000
#define S_MEM   16
#define D_DIM   128
#define C_CLS   6
#define M_IND   4
#define ROWS    128
#define NTHREADS 256
#define SCALE_INV 0.08838834764831845f

// SMEM byte offsets
#define OFF_XH  0
#define OFF_XL  32768
#define OFF_WH  65536
#define OFF_WL  98304
#define OFF_SF  131072                 // f32 [128][132]
#define SF_STR  132
#define OFF_SSM (OFF_SF + 128*SF_STR*4)    // f32 [32][132]
#define OFF_BIAS (OFF_SSM + 32*SF_STR*4)   // f32 [6][128]
#define OFF_IQ  (OFF_BIAS + 6*128*4)       // f32 [512]
#define OFF_IQB (OFF_IQ + 2048)            // f32 [16]
#define OFF_WOUT (OFF_IQB + 64)            // f32 [776]
#define OFF_SCR (OFF_WOUT + 3104)          // f32 [2048]
#define SMEM_TOTAL (OFF_SCR + 8192)        // 232032 <= 232448

__device__ __align__(16) float g_Iq[M_IND * D_DIM];
__device__ __align__(16) float g_Iqb[16];
// weight images, [n][k] row-major bf16 with 16B-chunk XOR swizzle
__device__ __align__(16) __nv_bfloat16 g_WH[7][16384];
__device__ __align__(16) __nv_bfloat16 g_WL[7][16384];

__host__ __device__ __forceinline__ int imgoff(int r, int c) {
    return r * 256 + (((c >> 3) ^ (r & 7)) << 4) + ((c & 7) << 1);
}

__device__ __forceinline__ uint32_t cvta_s(const void* p) {
    uint32_t a;
    asm("{ .reg .u64 t; cvta.to.shared.u64 t, %1; cvt.u32.u64 %0, t; }" : "=r"(a) : "l"(p));
    return a;
}
__device__ __forceinline__ void ldsm4(uint32_t* a, uint32_t addr) {
    asm volatile("ldmatrix.sync.aligned.m8n8.x4.shared.b16 {%0,%1,%2,%3}, [%4];"
        : "=r"(a[0]), "=r"(a[1]), "=r"(a[2]), "=r"(a[3]) : "r"(addr));
}
__device__ __forceinline__ void mma16816(float* c, const uint32_t* a, uint32_t b0, uint32_t b1) {
    asm volatile("mma.sync.aligned.m16n8k16.row.col.f32.bf16.bf16.f32 "
        "{%0,%1,%2,%3}, {%4,%5,%6,%7}, {%8,%9}, {%0,%1,%2,%3};"
        : "+f"(c[0]), "+f"(c[1]), "+f"(c[2]), "+f"(c[3])
        : "r"(a[0]), "r"(a[1]), "r"(a[2]), "r"(a[3]), "r"(b0), "r"(b1));
}
__device__ __forceinline__ void cp16(uint32_t dst, const void* src) {
    asm volatile("cp.async.cg.shared.global [%0], [%1], 16;" :: "r"(dst), "l"(src) : "memory");
}
__device__ __forceinline__ void cp_commit() { asm volatile("cp.async.commit_group;" ::: "memory"); }
__device__ __forceinline__ void cp_wait()   { asm volatile("cp.async.wait_group 0;" ::: "memory"); }

__device__ __forceinline__ uint32_t bf2bits(float a, float b) {
    __nv_bfloat162 p; p.x = __float2bfloat16(a); p.y = __float2bfloat16(b);
    return *(uint32_t*)&p;
}
// store 4 consecutive cols (c % 4 == 0) of hi+lo image with two 8B stores
__device__ __forceinline__ void img_st4(char* sm, int r, int c, float4 v) {
    int i = imgoff(r, c);
    float hx = __bfloat162float(__float2bfloat16(v.x));
    float hy = __bfloat162float(__float2bfloat16(v.y));
    float hz = __bfloat162float(__float2bfloat16(v.z));
    float hw = __bfloat162float(__float2bfloat16(v.w));
    uint2 hh, ll;
    hh.x = bf2bits(v.x, v.y);      hh.y = bf2bits(v.z, v.w);
    ll.x = bf2bits(v.x - hx, v.y - hy);
    ll.y = bf2bits(v.z - hz, v.w - hw);
    *(uint2*)(sm + OFF_XH + i) = hh;
    *(uint2*)(sm + OFF_XL + i) = ll;
}

// ---------------- prologs ----------------
__global__ void iq_kernel(const float* __restrict__ I, const float* __restrict__ Wq,
                          const float* __restrict__ bq) {
    int idx = blockIdx.x * blockDim.x + threadIdx.x;
    if (idx >= M_IND * D_DIM) return;
    int qi = idx / D_DIM, d = idx % D_DIM;
    float acc = bq[d];
    for (int k = 0; k < D_DIM; k++) acc += I[qi * D_DIM + k] * Wq[k * D_DIM + d];
    g_Iq[idx] = acc;
}
__global__ void iqb_kernel(const float* __restrict__ bk0) {
    int t = threadIdx.x;
    if (t < 16) {
        int qi = t >> 2, h = t & 3;
        float s = 0.f;
        for (int j = 0; j < 32; j++) s += g_Iq[qi * 128 + h * 32 + j] * bk0[h * 32 + j];
        g_Iqb[t] = s;
    }
}
__global__ void wconv_kernel(const float* W0, const float* W1, const float* W2, const float* W3,
                             const float* W4, const float* W5, const float* W6) {
    const float* W;
    int m = blockIdx.x;
    switch (m) { case 0: W = W0; break; case 1: W = W1; break; case 2: W = W2; break;
                 case 3: W = W3; break; case 4: W = W4; break; case 5: W = W5; break;
                 default: W = W6; }
    for (int i = threadIdx.x; i < 16384; i += blockDim.x) {
        int n = i >> 7, k = i & 127;
        float w = W[k * 128 + n];
        __nv_bfloat16 h = __float2bfloat16(w);
        int idx = n * 128 + (((k >> 3) ^ (n & 7)) << 3) + (k & 7);
        g_WH[m][idx] = h;
        g_WL[m][idx] = __float2bfloat16(w - __bfloat162float(h));
    }
}

__device__ __forceinline__ void lw_issue(char* sm, uint32_t sb, int widx, int tid) {
    const char* gh = (const char*)g_WH[widx];
    const char* gl = (const char*)g_WL[widx];
    uint32_t dh = sb + OFF_WH, dl = sb + OFF_WL;
#pragma unroll
    for (int i = 0; i < 8; i++) {
        int off = (tid + i * 256) * 16;
        cp16(dh + off, gh + off);
        cp16(dl + off, gl + off);
    }
    cp_commit();
}

__device__ __forceinline__ void gemm128(uint32_t xh, uint32_t xl, uint32_t wh, uint32_t wl,
                                        int wid, int lane, float acc[2][8][4]) {
    const int rg = wid >> 1, cg = wid & 1;
    const int lr = lane & 15, lh = lane >> 4;
    const int bn = (lane & 7) + ((lane >> 4) << 3);
    const int bh2 = (lane >> 3) & 1;
#pragma unroll
    for (int ks = 0; ks < 8; ks++) {
        uint32_t ah[2][4], al[2][4];
#pragma unroll
        for (int rt = 0; rt < 2; rt++) {
            int r = rg * 32 + rt * 16 + lr;
            uint32_t off = (uint32_t)(r * 256 + (((ks * 2 + lh) ^ (r & 7)) << 4));
            ldsm4(ah[rt], xh + off);
            ldsm4(al[rt], xl + off);
        }
#pragma unroll
        for (int ntp = 0; ntp < 4; ntp++) {
            int n = cg * 64 + ntp * 16 + bn;
            uint32_t boff = (uint32_t)(n * 256 + (((ks * 2 + bh2) ^ (n & 7)) << 4));
            uint32_t bh[4], bl[4];
            ldsm4(bh, wh + boff);
            ldsm4(bl, wl + boff);
#pragma unroll
            for (int rt = 0; rt < 2; rt++) {
                mma16816(acc[rt][2 * ntp],     ah[rt], bh[0], bh[1]);
                mma16816(acc[rt][2 * ntp],     al[rt], bh[0], bh[1]);
                mma16816(acc[rt][2 * ntp],     ah[rt], bl[0], bl[1]);
                mma16816(acc[rt][2 * ntp + 1], ah[rt], bh[2], bh[3]);
                mma16816(acc[rt][2 * ntp + 1], al[rt], bh[2], bh[3]);
                mma16816(acc[rt][2 * ntp + 1], ah[rt], bl[2], bl[3]);
            }
        }
    }
}

__device__ __forceinline__ void gemm32(uint32_t xh, uint32_t xl, uint32_t wh, uint32_t wl,
                                       int wid, int lane, float acc[4][4]) {
    const int rt = wid >> 2, cg = wid & 3;
    const int lr = lane & 15, lh = lane >> 4;
    const int bn = (lane & 7) + ((lane >> 4) << 3);
    const int bh2 = (lane >> 3) & 1;
#pragma unroll
    for (int ks = 0; ks < 8; ks++) {
        uint32_t ah[4], al[4];
        int r = rt * 16 + lr;
        uint32_t off = (uint32_t)(r * 256 + (((ks * 2 + lh) ^ (r & 7)) << 4));
        ldsm4(ah, xh + off);
        ldsm4(al, xl + off);
#pragma unroll
        for (int ntp = 0; ntp < 2; ntp++) {
            int n = cg * 32 + ntp * 16 + bn;
            uint32_t boff = (uint32_t)(n * 256 + (((ks * 2 + bh2) ^ (n & 7)) << 4));
            uint32_t bh[4], bl[4];
            ldsm4(bh, wh + boff);
            ldsm4(bl, wl + boff);
            mma16816(acc[2 * ntp],     ah, bh[0], bh[1]);
            mma16816(acc[2 * ntp],     al, bh[0], bh[1]);
            mma16816(acc[2 * ntp],     ah, bl[0], bl[1]);
            mma16816(acc[2 * ntp + 1], ah, bh[2], bh[3]);
            mma16816(acc[2 * ntp + 1], al, bh[2], bh[3]);
            mma16816(acc[2 * ntp + 1], ah, bl[2], bl[3]);
        }
    }
}

extern "C" __global__ void __launch_bounds__(NTHREADS, 1)
whatsnet_mma(const float* __restrict__ vfeat, const int* __restrict__ member_idx,
             const int* __restrict__ labels,
             const float* __restrict__ Wout, const float* __restrict__ bout,
             const float* __restrict__ bv0, const float* __restrict__ bo0,
             const float* __restrict__ bq1, const float* __restrict__ bk1,
             const float* __restrict__ bv1, const float* __restrict__ bo1,
             float* __restrict__ out, int n_nodes, long long out_capacity)
{
    extern __shared__ char sm[];
    const int tid = threadIdx.x;
    const int wid = tid >> 5, lane = tid & 31;
    const int rowbase = blockIdx.x * ROWS;
    const uint32_t sb = cvta_s(sm);
    const uint32_t xh = sb + OFF_XH, xl = sb + OFF_XL;
    const uint32_t wh = sb + OFF_WH, wl = sb + OFF_WL;

    float* sF   = (float*)(sm + OFF_SF);
    float* sSm  = (float*)(sm + OFF_SSM);     // O0; later V1f
    // K1f [32][132] scratch in DEAD X-image rows 34+ (bytes 8704..25600 of XH).
    // Must NOT overlap bytes 0..8192 (Hset image rows 0..31, live until V1 gemm).
    float* sK1  = (float*)(sm + OFF_XH + 8704);
    float* sBias= (float*)(sm + OFF_BIAS);
    float* sIq  = (float*)(sm + OFF_IQ);
    float* sIqb = (float*)(sm + OFF_IQB);
    float* sWo  = (float*)(sm + OFF_WOUT);
    float* sScr = (float*)(sm + OFF_SCR);

    // constants
    if (tid < 128) {
        sBias[0 * 128 + tid] = bv0[tid];
        sBias[1 * 128 + tid] = bo0[tid];
        sBias[2 * 128 + tid] = bq1[tid];
        sBias[3 * 128 + tid] = bk1[tid];
        sBias[4 * 128 + tid] = bv1[tid];
        sBias[5 * 128 + tid] = bo1[tid];
    }
    for (int i = tid; i < 512; i += NTHREADS) sIq[i] = g_Iq[i];
    if (tid < 16) sIqb[tid] = g_Iqb[tid];
    for (int i = tid; i < 768; i += NTHREADS) sWo[i] = Wout[i];
    if (tid < 6) sWo[768 + tid] = bout[tid];

    lw_issue(sm, sb, 0, tid);

    // gather -> X images
    for (int r = wid; r < ROWS; r += 8) {
        int n = member_idx[rowbase + r];
        if (n < 0) n = 0;
        if (n >= n_nodes) n = n_nodes - 1;
        float4 v = *(const float4*)(vfeat + (size_t)n * D_DIM + lane * 4);
        img_st4(sm, r, lane * 4, v);
    }
    cp_wait();
    __syncthreads();

    const int l4 = lane >> 2, c2 = (lane & 3) * 2;
    const int rg = wid >> 1, cg = wid & 1;

    float acc[2][8][4];
    float acc32[4][4];

    // ===== K0 = X@Wk0 =====
#pragma unroll
    for (int i = 0; i < 2; i++)
#pragma unroll
        for (int j = 0; j < 8; j++)
#pragma unroll
            for (int q = 0; q < 4; q++) acc[i][j][q] = 0.f;
    gemm128(xh, xl, wh, wl, wid, lane, acc);
    __syncthreads();
    lw_issue(sm, sb, 1, tid);
#pragma unroll
    for (int rt = 0; rt < 2; rt++)
#pragma unroll
        for (int nt = 0; nt < 8; nt++) {
            int r = rg * 32 + rt * 16 + l4, c = cg * 64 + nt * 8 + c2;
            sF[r * SF_STR + c]       = acc[rt][nt][0];
            sF[r * SF_STR + c + 1]   = acc[rt][nt][1];
            sF[(r + 8) * SF_STR + c]     = acc[rt][nt][2];
            sF[(r + 8) * SF_STR + c + 1] = acc[rt][nt][3];
        }
    __syncthreads();

    // scores0
#pragma unroll 1
    for (int it = 0; it < 8; it++) {
        int idx = tid + it * 256;
        int s = idx & 15, qi = (idx >> 4) & 3, h = (idx >> 6) & 3, e = idx >> 8;
        const float4* qv = (const float4*)&sIq[qi * 128 + h * 32];
        const float4* kv = (const float4*)&sF[(e * 16 + s) * SF_STR + h * 32];
        float dot = sIqb[qi * 4 + h];
#pragma unroll
        for (int d4 = 0; d4 < 8; d4++) {
            float4 q = qv[d4], k = kv[d4];
            dot += q.x * k.x + q.y * k.y + q.z * k.z + q.w * k.w;
        }
        sScr[idx] = dot * SCALE_INV;
    }
    cp_wait();
    __syncthreads();

    // ===== V0 = X@Wv0 + bv0 -> sF =====
#pragma unroll
    for (int i = 0; i < 2; i++)
#pragma unroll
        for (int j = 0; j < 8; j++)
#pragma unroll
            for (int q = 0; q < 4; q++) acc[i][j][q] = 0.f;
    gemm128(xh, xl, wh, wl, wid, lane, acc);
    __syncthreads();
    lw_issue(sm, sb, 2, tid);
#pragma unroll
    for (int rt = 0; rt < 2; rt++)
#pragma unroll
        for (int nt = 0; nt < 8; nt++) {
            int r = rg * 32 + rt * 16 + l4, c = cg * 64 + nt * 8 + c2;
            sF[r * SF_STR + c]       = acc[rt][nt][0] + sBias[c];
            sF[r * SF_STR + c + 1]   = acc[rt][nt][1] + sBias[c + 1];
            sF[(r + 8) * SF_STR + c]     = acc[rt][nt][2] + sBias[c];
            sF[(r + 8) * SF_STR + c + 1] = acc[rt][nt][3] + sBias[c + 1];
        }
    // softmax0
    if (tid < 128) {
        float* p = &sScr[tid * 16];
        float mx = p[0];
#pragma unroll
        for (int i = 1; i < 16; i++) mx = fmaxf(mx, p[i]);
        float sum = 0.f;
#pragma unroll
        for (int i = 0; i < 16; i++) { float ex = expf(p[i] - mx); p[i] = ex; sum += ex; }
        float inv = 1.f / sum;
#pragma unroll
        for (int i = 0; i < 16; i++) p[i] *= inv;
    }
    __syncthreads();

    // O0 = Iq + A @ V0f -> sSm (32 rows), float4-vectorized
#pragma unroll
    for (int it = 0; it < 4; it++) {
        int idx = tid + it * 256;             // 1024 float4 items
        int d = (idx & 31) * 4, row = idx >> 5;
        int qi = row & 3, e = row >> 2, h = d >> 5;
        float4 o = *(const float4*)&sIq[qi * 128 + d];
        const float* A = &sScr[((e * 4 + h) * 4 + qi) * 16];
        const float* vv = &sF[(e * 16) * SF_STR + d];
#pragma unroll
        for (int s = 0; s < 16; s++) {
            float4 v = *(const float4*)&vv[s * SF_STR];
            float a = A[s];
            o.x += a * v.x; o.y += a * v.y; o.z += a * v.z; o.w += a * v.w;
        }
        *(float4*)&sSm[row * SF_STR + d] = o;
    }
    cp_wait();
    __syncthreads();

    // ===== Q1 = X@Wq1 + bq1 -> sF =====
#pragma unroll
    for (int i = 0; i < 2; i++)
#pragma unroll
        for (int j = 0; j < 8; j++)
#pragma unroll
            for (int q = 0; q < 4; q++) acc[i][j][q] = 0.f;
    gemm128(xh, xl, wh, wl, wid, lane, acc);
    __syncthreads();                       // X dead now
    lw_issue(sm, sb, 3, tid);
#pragma unroll
    for (int rt = 0; rt < 2; rt++)
#pragma unroll
        for (int nt = 0; nt < 8; nt++) {
            int r = rg * 32 + rt * 16 + l4, c = cg * 64 + nt * 8 + c2;
            sF[r * SF_STR + c]       = acc[rt][nt][0] + sBias[2 * 128 + c];
            sF[r * SF_STR + c + 1]   = acc[rt][nt][1] + sBias[2 * 128 + c + 1];
            sF[(r + 8) * SF_STR + c]     = acc[rt][nt][2] + sBias[2 * 128 + c];
            sF[(r + 8) * SF_STR + c + 1] = acc[rt][nt][3] + sBias[2 * 128 + c + 1];
        }
    // O0 -> X image rows 0..31 (vectorized)
#pragma unroll
    for (int it = 0; it < 4; it++) {
        int i = tid + it * 256;               // 1024 float4 items
        int r = i >> 5, c = (i & 31) * 4;
        img_st4(sm, r, c, *(const float4*)&sSm[r * SF_STR + c]);
    }
    cp_wait();
    __syncthreads();

    // ===== T0 = O0@Wo0 ; Hset = O0 + relu(T0+bo0) -> image rows 0..31 =====
#pragma unroll
    for (int j = 0; j < 4; j++)
#pragma unroll
        for (int q = 0; q < 4; q++) acc32[j][q] = 0.f;
    gemm32(xh, xl, wh, wl, wid, lane, acc32);
    __syncthreads();
    lw_issue(sm, sb, 4, tid);
    {
        int rt = wid >> 2, cgs = wid & 3;
        int r = rt * 16 + l4;
#pragma unroll
        for (int nt = 0; nt < 4; nt++) {
            int c = cgs * 32 + nt * 8 + c2;
            float v0 = sSm[r * SF_STR + c]     + fmaxf(acc32[nt][0] + sBias[128 + c], 0.f);
            float v1 = sSm[r * SF_STR + c + 1] + fmaxf(acc32[nt][1] + sBias[128 + c + 1], 0.f);
            int i0 = imgoff(r, c);
            *(uint32_t*)(sm + OFF_XH + i0) = bf2bits(v0, v1);
            float h0 = __bfloat162float(__float2bfloat16(v0));
            float h1 = __bfloat162float(__float2bfloat16(v1));
            *(uint32_t*)(sm + OFF_XL + i0) = bf2bits(v0 - h0, v1 - h1);
            float w0 = sSm[(r + 8) * SF_STR + c]     + fmaxf(acc32[nt][2] + sBias[128 + c], 0.f);
            float w1 = sSm[(r + 8) * SF_STR + c + 1] + fmaxf(acc32[nt][3] + sBias[128 + c + 1], 0.f);
            int i1 = imgoff(r + 8, c);
            *(uint32_t*)(sm + OFF_XH + i1) = bf2bits(w0, w1);
            float g0 = __bfloat162float(__float2bfloat16(w0));
            float g1 = __bfloat162float(__float2bfloat16(w1));
            *(uint32_t*)(sm + OFF_XL + i1) = bf2bits(w0 - g0, w1 - g1);
        }
    }
    cp_wait();
    __syncthreads();

    // ===== K1 = Hset@Wk1 + bk1 -> sK1 (disjoint dead-X scratch) =====
#pragma unroll
    for (int j = 0; j < 4; j++)
#pragma unroll
        for (int q = 0; q < 4; q++) acc32[j][q] = 0.f;
    gemm32(xh, xl, wh, wl, wid, lane, acc32);
    __syncthreads();
    lw_issue(sm, sb, 5, tid);
    {
        int rt = wid >> 2, cgs = wid & 3;
        int r = rt * 16 + l4;
#pragma unroll
        for (int nt = 0; nt < 4; nt++) {
            int c = cgs * 32 + nt * 8 + c2;
            sK1[r * SF_STR + c]       = acc32[nt][0] + sBias[3 * 128 + c];
            sK1[r * SF_STR + c + 1]   = acc32[nt][1] + sBias[3 * 128 + c + 1];
            sK1[(r + 8) * SF_STR + c]     = acc32[nt][2] + sBias[3 * 128 + c];
            sK1[(r + 8) * SF_STR + c + 1] = acc32[nt][3] + sBias[3 * 128 + c + 1];
        }
    }
    cp_wait();
    __syncthreads();

    // ===== V1 = Hset@Wv1 + bv1 -> sSm (O0 dead) =====
#pragma unroll
    for (int j = 0; j < 4; j++)
#pragma unroll
        for (int q = 0; q < 4; q++) acc32[j][q] = 0.f;
    gemm32(xh, xl, wh, wl, wid, lane, acc32);
    __syncthreads();
    lw_issue(sm, sb, 6, tid);
    {
        int rt = wid >> 2, cgs = wid & 3;
        int r = rt * 16 + l4;
#pragma unroll
        for (int nt = 0; nt < 4; nt++) {
            int c = cgs * 32 + nt * 8 + c2;
            sSm[r * SF_STR + c]       = acc32[nt][0] + sBias[4 * 128 + c];
            sSm[r * SF_STR + c + 1]   = acc32[nt][1] + sBias[4 * 128 + c + 1];
            sSm[(r + 8) * SF_STR + c]     = acc32[nt][2] + sBias[4 * 128 + c];
            sSm[(r + 8) * SF_STR + c + 1] = acc32[nt][3] + sBias[4 * 128 + c + 1];
        }
    }
    __syncthreads();

    // scores1: ((e*4+h)*16+q)*4+k  (keys from sK1)
#pragma unroll 1
    for (int it = 0; it < 8; it++) {
        int idx = tid + it * 256;
        int k = idx & 3, q = (idx >> 2) & 15, h = (idx >> 6) & 3, e = idx >> 8;
        const float4* qv = (const float4*)&sF[(e * 16 + q) * SF_STR + h * 32];
        const float4* kv = (const float4*)&sK1[(e * 4 + k) * SF_STR + h * 32];
        float dot = 0.f;
#pragma unroll
        for (int d4 = 0; d4 < 8; d4++) {
            float4 qq = qv[d4], kk = kv[d4];
            dot += qq.x * kk.x + qq.y * kk.y + qq.z * kk.z + qq.w * kk.w;
        }
        sScr[idx] = dot * SCALE_INV;
    }
    __syncthreads();
    for (int rr = tid; rr < 512; rr += 256) {
        float* p = &sScr[rr * 4];
        float mx = fmaxf(fmaxf(p[0], p[1]), fmaxf(p[2], p[3]));
        float e0 = expf(p[0] - mx), e1 = expf(p[1] - mx), e2 = expf(p[2] - mx), e3 = expf(p[3] - mx);
        float inv = 1.f / (e0 + e1 + e2 + e3);
        p[0] = e0 * inv; p[1] = e1 * inv; p[2] = e2 * inv; p[3] = e3 * inv;
    }
    __syncthreads();

    // O = Q1 + A1@V1f (V1f in sSm), fused: sF update + X image write (K1f dead)
#pragma unroll
    for (int it = 0; it < 16; it++) {
        int idx = tid + it * 256;             // 4096 float4 items
        int d = (idx & 31) * 4, row = idx >> 5;
        int q = row & 15, e = row >> 4, h = d >> 5;
        float4 o = *(const float4*)&sF[row * SF_STR + d];
        const float* A = &sScr[((e * 4 + h) * 16 + q) * 4];
#pragma unroll
        for (int k = 0; k < 4; k++) {
            float4 v = *(const float4*)&sSm[(e * 4 + k) * SF_STR + d];
            float a = A[k];
            o.x += a * v.x; o.y += a * v.y; o.z += a * v.z; o.w += a * v.w;
        }
        *(float4*)&sF[row * SF_STR + d] = o;
        img_st4(sm, row, d, o);
    }
    cp_wait();
    __syncthreads();

    // ===== T1 = O@Wo1 ; final = O + relu(T1+bo1) -> sF in place =====
#pragma unroll
    for (int i = 0; i < 2; i++)
#pragma unroll
        for (int j = 0; j < 8; j++)
#pragma unroll
            for (int q = 0; q < 4; q++) acc[i][j][q] = 0.f;
    gemm128(xh, xl, wh, wl, wid, lane, acc);
#pragma unroll
    for (int rt = 0; rt < 2; rt++)
#pragma unroll
        for (int nt = 0; nt < 8; nt++) {
            int r = rg * 32 + rt * 16 + l4, c = cg * 64 + nt * 8 + c2;
            sF[r * SF_STR + c]       += fmaxf(acc[rt][nt][0] + sBias[5 * 128 + c], 0.f);
            sF[r * SF_STR + c + 1]   += fmaxf(acc[rt][nt][1] + sBias[5 * 128 + c + 1], 0.f);
            sF[(r + 8) * SF_STR + c]     += fmaxf(acc[rt][nt][2] + sBias[5 * 128 + c], 0.f);
            sF[(r + 8) * SF_STR + c + 1] += fmaxf(acc[rt][nt][3] + sBias[5 * 128 + c + 1], 0.f);
        }
    __syncthreads();

    // logits: 2 threads/row, 3 cols each
    {
        int r = tid >> 1, cb = (tid & 1) * 3;
        float a0 = sWo[768 + cb], a1 = sWo[768 + cb + 1], a2 = sWo[768 + cb + 2];
        const float4* xr = (const float4*)&sF[r * SF_STR];
#pragma unroll
        for (int k4 = 0; k4 < 32; k4++) {
            float4 x = xr[k4];
            const float* w0 = &sWo[(k4 * 4 + 0) * C_CLS + cb];
            const float* w1 = &sWo[(k4 * 4 + 1) * C_CLS + cb];
            const float* w2 = &sWo[(k4 * 4 + 2) * C_CLS + cb];
            const float* w3 = &sWo[(k4 * 4 + 3) * C_CLS + cb];
            a0 += x.x * w0[0] + x.y * w1[0] + x.z * w2[0] + x.w * w3[0];
            a1 += x.x * w0[1] + x.y * w1[1] + x.z * w2[1] + x.w * w3[1];
            a2 += x.x * w0[2] + x.y * w1[2] + x.z * w2[2] + x.w * w3[2];
        }
        long long off = (long long)(rowbase + r) * C_CLS + cb;
        if (off + 2 < out_capacity) {
            out[off] = a0; out[off + 1] = a1; out[off + 2] = a2;
        }
    }
    long long lab_base = (long long)E_EDGES * S_MEM * C_CLS;
    if (out_capacity >= lab_base + (long long)E_EDGES * S_MEM) {
        for (int r = tid; r < ROWS; r += 256)
            out[lab_base + rowbase + r] = (float)labels[rowbase + r];
    }
}

extern "C" void kernel_launch(void* const* d_in, const int* in_sizes, int n_in,
                              void* d_out, int out_size) {
    const float* Ws[8] = {0,0,0,0,0,0,0,0};
    const float* Bs[8] = {0,0,0,0,0,0,0,0};
    const float* vfeat = 0; const float* Iin = 0;
    const float* Wout = 0;  const float* bout = 0;
    const int* member_idx = 0; const int* labels = 0;
    int wi = 0, bi = 0, n_nodes = 500000;
    for (int i = 0; i < n_in; i++) {
        int sz = in_sizes[i];
        if (sz == 500000 * 128)      { vfeat = (const float*)d_in[i]; n_nodes = sz / D_DIM; }
        else if (sz == E_EDGES * S_MEM) {
            if (!member_idx) member_idx = (const int*)d_in[i];
            else if (!labels) labels = (const int*)d_in[i];
        }
        else if (sz == M_IND * D_DIM) Iin = (const float*)d_in[i];
        else if (sz == D_DIM * C_CLS) Wout = (const float*)d_in[i];
        else if (sz == C_CLS)         bout = (const float*)d_in[i];
        else if (sz == D_DIM * D_DIM) { if (wi < 8) Ws[wi++] = (const float*)d_in[i]; }
        else if (sz == D_DIM)         { if (bi < 8) Bs[bi++] = (const float*)d_in[i]; }
    }
    if (!vfeat || !member_idx || !labels || !Iin || !Wout || !bout || wi != 8 || bi != 8) {
        vfeat = (const float*)d_in[0]; member_idx = (const int*)d_in[1];
        labels = (const int*)d_in[2];  Iin = (const float*)d_in[3];
        Wout = (const float*)d_in[4];  bout = (const float*)d_in[5];
        for (int j = 0; j < 8; j++) { Ws[j] = (const float*)d_in[6 + 2 * j]; Bs[j] = (const float*)d_in[7 + 2 * j]; }
        n_nodes = in_sizes[0] / D_DIM;
    }
    const float *Wq0 = Ws[0], *Wk0 = Ws[1], *Wv0 = Ws[2], *Wo0 = Ws[3];
    const float *Wq1 = Ws[4], *Wk1 = Ws[5], *Wv1 = Ws[6], *Wo1 = Ws[7];
    const float *bq0 = Bs[0], *bk0 = Bs[1], *bv0 = Bs[2], *bo0 = Bs[3];
    const float *bq1 = Bs[4], *bk1 = Bs[5], *bv1 = Bs[6], *bo1 = Bs[7];

    cudaFuncSetAttribute(whatsnet_mma, cudaFuncAttributeMaxDynamicSharedMemorySize, SMEM_TOTAL);

    iq_kernel<<<2, 256>>>(Iin, Wq0, bq0);
    iqb_kernel<<<1, 32>>>(bk0);
    wconv_kernel<<<7, 256>>>(Wk0, Wv0, Wq1, Wo0, Wk1, Wv1, Wo1);

    whatsnet_mma<<<E_EDGES * S_MEM / ROWS, NTHREADS, SMEM_TOTAL>>>(
        vfeat, member_idx, labels, Wout, bout,
        bv0, bo0, bq1, bk1, bv1, bo1,
        (float*)d_out, n_nodes, (long long)out_size);
}

// round 13
// speedup vs baseline: 1.7191x; 1.1286x over previous
#include <cuda_runtime.h>
#include <cuda_bf16.h>
#include <math.h>
#include <stdint.h>

#define E_EDGES 100000
#define S_MEM   16
#define D_DIM   128
#define C_CLS   6
#define M_IND   4
#define ROWS    128
#define NTH     512
#define SCALE_INV 0.08838834764831845f

// SMEM byte offsets
#define OFF_XH  0
#define OFF_XL  32768
#define OFF_WH  65536
#define OFF_WL  98304
#define OFF_SF  131072                 // f32 [128][132]
#define SF_STR  132
#define OFF_SSM (OFF_SF + 128*SF_STR*4)    // f32 [32][132]
#define OFF_BIAS (OFF_SSM + 32*SF_STR*4)   // f32 [6][128]
#define OFF_IQ  (OFF_BIAS + 6*128*4)       // f32 [512]
#define OFF_IQB (OFF_IQ + 2048)            // f32 [16]
#define OFF_WOUT (OFF_IQB + 64)            // f32 [776]
#define OFF_SCR (OFF_WOUT + 3104)          // f32 [2048]
#define SMEM_TOTAL (OFF_SCR + 8192)        // 232032 <= 232448

__device__ __align__(16) float g_Iq[M_IND * D_DIM];
__device__ __align__(16) float g_Iqb[16];
__device__ __align__(16) __nv_bfloat16 g_WH[7][16384];
__device__ __align__(16) __nv_bfloat16 g_WL[7][16384];

__host__ __device__ __forceinline__ int imgoff(int r, int c) {
    return r * 256 + (((c >> 3) ^ (r & 7)) << 4) + ((c & 7) << 1);
}

__device__ __forceinline__ uint32_t cvta_s(const void* p) {
    uint32_t a;
    asm("{ .reg .u64 t; cvta.to.shared.u64 t, %1; cvt.u32.u64 %0, t; }" : "=r"(a) : "l"(p));
    return a;
}
__device__ __forceinline__ void ldsm4(uint32_t* a, uint32_t addr) {
    asm volatile("ldmatrix.sync.aligned.m8n8.x4.shared.b16 {%0,%1,%2,%3}, [%4];"
        : "=r"(a[0]), "=r"(a[1]), "=r"(a[2]), "=r"(a[3]) : "r"(addr));
}
__device__ __forceinline__ void mma16816(float* c, const uint32_t* a, uint32_t b0, uint32_t b1) {
    asm volatile("mma.sync.aligned.m16n8k16.row.col.f32.bf16.bf16.f32 "
        "{%0,%1,%2,%3}, {%4,%5,%6,%7}, {%8,%9}, {%0,%1,%2,%3};"
        : "+f"(c[0]), "+f"(c[1]), "+f"(c[2]), "+f"(c[3])
        : "r"(a[0]), "r"(a[1]), "r"(a[2]), "r"(a[3]), "r"(b0), "r"(b1));
}
__device__ __forceinline__ void cp16(uint32_t dst, const void* src) {
    asm volatile("cp.async.cg.shared.global [%0], [%1], 16;" :: "r"(dst), "l"(src) : "memory");
}
__device__ __forceinline__ void cp_commit() { asm volatile("cp.async.commit_group;" ::: "memory"); }
__device__ __forceinline__ void cp_wait()   { asm volatile("cp.async.wait_group 0;" ::: "memory"); }

__device__ __forceinline__ uint32_t bf2bits(float a, float b) {
    __nv_bfloat162 p; p.x = __float2bfloat16(a); p.y = __float2bfloat16(b);
    return *(uint32_t*)&p;
}
__device__ __forceinline__ void img_st4(char* sm, int r, int c, float4 v) {
    int i = imgoff(r, c);
    float hx = __bfloat162float(__float2bfloat16(v.x));
    float hy = __bfloat162float(__float2bfloat16(v.y));
    float hz = __bfloat162float(__float2bfloat16(v.z));
    float hw = __bfloat162float(__float2bfloat16(v.w));
    uint2 hh, ll;
    hh.x = bf2bits(v.x, v.y);      hh.y = bf2bits(v.z, v.w);
    ll.x = bf2bits(v.x - hx, v.y - hy);
    ll.y = bf2bits(v.z - hz, v.w - hw);
    *(uint2*)(sm + OFF_XH + i) = hh;
    *(uint2*)(sm + OFF_XL + i) = ll;
}

// ---------------- prologs ----------------
__global__ void iq_kernel(const float* __restrict__ I, const float* __restrict__ Wq,
                          const float* __restrict__ bq) {
    int idx = blockIdx.x * blockDim.x + threadIdx.x;
    if (idx >= M_IND * D_DIM) return;
    int qi = idx / D_DIM, d = idx % D_DIM;
    float acc = bq[d];
    for (int k = 0; k < D_DIM; k++) acc += I[qi * D_DIM + k] * Wq[k * D_DIM + d];
    g_Iq[idx] = acc;
}
__global__ void iqb_kernel(const float* __restrict__ bk0) {
    int t = threadIdx.x;
    if (t < 16) {
        int qi = t >> 2, h = t & 3;
        float s = 0.f;
        for (int j = 0; j < 32; j++) s += g_Iq[qi * 128 + h * 32 + j] * bk0[h * 32 + j];
        g_Iqb[t] = s;
    }
}
__global__ void wconv_kernel(const float* W0, const float* W1, const float* W2, const float* W3,
                             const float* W4, const float* W5, const float* W6) {
    const float* W;
    int m = blockIdx.x;
    switch (m) { case 0: W = W0; break; case 1: W = W1; break; case 2: W = W2; break;
                 case 3: W = W3; break; case 4: W = W4; break; case 5: W = W5; break;
                 default: W = W6; }
    for (int i = threadIdx.x; i < 16384; i += blockDim.x) {
        int n = i >> 7, k = i & 127;
        float w = W[k * 128 + n];
        __nv_bfloat16 h = __float2bfloat16(w);
        int idx = n * 128 + (((k >> 3) ^ (n & 7)) << 3) + (k & 7);
        g_WH[m][idx] = h;
        g_WL[m][idx] = __float2bfloat16(w - __bfloat162float(h));
    }
}

__device__ __forceinline__ void lw_issue(char* sm, uint32_t sb, int widx, int tid) {
    const char* gh = (const char*)g_WH[widx];
    const char* gl = (const char*)g_WL[widx];
    uint32_t dh = sb + OFF_WH, dl = sb + OFF_WL;
#pragma unroll
    for (int i = 0; i < 4; i++) {
        int off = (tid + i * 512) * 16;
        cp16(dh + off, gh + off);
        cp16(dl + off, gl + off);
    }
    cp_commit();
}

// 128x128x128 GEMM, 16 warps: rowgroup wid>>1 (16 rows), colgroup wid&1 (64 cols)
__device__ __forceinline__ void gemm128(uint32_t xh, uint32_t xl, uint32_t wh, uint32_t wl,
                                        int wid, int lane, float acc[8][4]) {
    const int rg = wid >> 1, cg = wid & 1;
    const int lr = lane & 15, lh = lane >> 4;
    const int bn = (lane & 7) + ((lane >> 4) << 3);
    const int bh2 = (lane >> 3) & 1;
#pragma unroll
    for (int ks = 0; ks < 8; ks++) {
        uint32_t ah[4], al[4];
        int r = rg * 16 + lr;
        uint32_t off = (uint32_t)(r * 256 + (((ks * 2 + lh) ^ (r & 7)) << 4));
        ldsm4(ah, xh + off);
        ldsm4(al, xl + off);
#pragma unroll
        for (int ntp = 0; ntp < 4; ntp++) {
            int n = cg * 64 + ntp * 16 + bn;
            uint32_t boff = (uint32_t)(n * 256 + (((ks * 2 + bh2) ^ (n & 7)) << 4));
            uint32_t bh[4], bl[4];
            ldsm4(bh, wh + boff);
            ldsm4(bl, wl + boff);
            mma16816(acc[2 * ntp],     ah, bh[0], bh[1]);
            mma16816(acc[2 * ntp],     al, bh[0], bh[1]);
            mma16816(acc[2 * ntp],     ah, bl[0], bl[1]);
            mma16816(acc[2 * ntp + 1], ah, bh[2], bh[3]);
            mma16816(acc[2 * ntp + 1], al, bh[2], bh[3]);
            mma16816(acc[2 * ntp + 1], ah, bl[2], bl[3]);
        }
    }
}

// 32x128x128 GEMM, 16 warps: rowtile wid>>3 (16 rows), colgroup wid&7 (16 cols)
__device__ __forceinline__ void gemm32(uint32_t xh, uint32_t xl, uint32_t wh, uint32_t wl,
                                       int wid, int lane, float acc[2][4]) {
    const int rt = wid >> 3, cg8 = wid & 7;
    const int lr = lane & 15, lh = lane >> 4;
    const int bn = (lane & 7) + ((lane >> 4) << 3);
    const int bh2 = (lane >> 3) & 1;
#pragma unroll
    for (int ks = 0; ks < 8; ks++) {
        uint32_t ah[4], al[4];
        int r = rt * 16 + lr;
        uint32_t off = (uint32_t)(r * 256 + (((ks * 2 + lh) ^ (r & 7)) << 4));
        ldsm4(ah, xh + off);
        ldsm4(al, xl + off);
        int n = cg8 * 16 + bn;
        uint32_t boff = (uint32_t)(n * 256 + (((ks * 2 + bh2) ^ (n & 7)) << 4));
        uint32_t bh[4], bl[4];
        ldsm4(bh, wh + boff);
        ldsm4(bl, wl + boff);
        mma16816(acc[0], ah, bh[0], bh[1]);
        mma16816(acc[0], al, bh[0], bh[1]);
        mma16816(acc[0], ah, bl[0], bl[1]);
        mma16816(acc[1], ah, bh[2], bh[3]);
        mma16816(acc[1], al, bh[2], bh[3]);
        mma16816(acc[1], ah, bl[2], bl[3]);
    }
}

extern "C" __global__ void __launch_bounds__(NTH, 1)
whatsnet_mma(const float* __restrict__ vfeat, const int* __restrict__ member_idx,
             const int* __restrict__ labels,
             const float* __restrict__ Wout, const float* __restrict__ bout,
             const float* __restrict__ bv0, const float* __restrict__ bo0,
             const float* __restrict__ bq1, const float* __restrict__ bk1,
             const float* __restrict__ bv1, const float* __restrict__ bo1,
             float* __restrict__ out, int n_nodes, long long out_capacity)
{
    extern __shared__ char sm[];
    const int tid = threadIdx.x;
    const int wid = tid >> 5, lane = tid & 31;
    const int rowbase = blockIdx.x * ROWS;
    const uint32_t sb = cvta_s(sm);
    const uint32_t xh = sb + OFF_XH, xl = sb + OFF_XL;
    const uint32_t wh = sb + OFF_WH, wl = sb + OFF_WL;

    float* sF   = (float*)(sm + OFF_SF);
    float* sSm  = (float*)(sm + OFF_SSM);     // O0; later V1f
    float* sK1  = (float*)(sm + OFF_XH + 8704);  // K1f scratch, disjoint from image rows 0..31
    float* sBias= (float*)(sm + OFF_BIAS);
    float* sIq  = (float*)(sm + OFF_IQ);
    float* sIqb = (float*)(sm + OFF_IQB);
    float* sWo  = (float*)(sm + OFF_WOUT);
    float* sScr = (float*)(sm + OFF_SCR);

    // constants
    if (tid < 128) {
        sBias[0 * 128 + tid] = bv0[tid];
        sBias[1 * 128 + tid] = bo0[tid];
        sBias[2 * 128 + tid] = bq1[tid];
        sBias[3 * 128 + tid] = bk1[tid];
        sBias[4 * 128 + tid] = bv1[tid];
        sBias[5 * 128 + tid] = bo1[tid];
    }
    if (tid < 512) sIq[tid] = g_Iq[tid];
    if (tid < 16) sIqb[tid] = g_Iqb[tid];
    for (int i = tid; i < 768; i += NTH) sWo[i] = Wout[i];
    if (tid < 6) sWo[768 + tid] = bout[tid];

    lw_issue(sm, sb, 0, tid);

    // gather -> X images (16 warps x 8 rows)
    for (int r = wid; r < ROWS; r += 16) {
        int n = member_idx[rowbase + r];
        if (n < 0) n = 0;
        if (n >= n_nodes) n = n_nodes - 1;
        float4 v = *(const float4*)(vfeat + (size_t)n * D_DIM + lane * 4);
        img_st4(sm, r, lane * 4, v);
    }
    cp_wait();
    __syncthreads();

    const int l4 = lane >> 2, c2 = (lane & 3) * 2;
    const int rg = wid >> 1, cg = wid & 1;

    float acc[8][4];
    float acc32[2][4];

    // ===== K0 = X@Wk0 -> sF (store hoisted into gemm region; sF dead before) =====
#pragma unroll
    for (int j = 0; j < 8; j++)
#pragma unroll
        for (int q = 0; q < 4; q++) acc[j][q] = 0.f;
    gemm128(xh, xl, wh, wl, wid, lane, acc);
    {
        int r = rg * 16 + l4;
#pragma unroll
        for (int nt = 0; nt < 8; nt++) {
            int c = cg * 64 + nt * 8 + c2;
            sF[r * SF_STR + c]       = acc[nt][0];
            sF[r * SF_STR + c + 1]   = acc[nt][1];
            sF[(r + 8) * SF_STR + c]     = acc[nt][2];
            sF[(r + 8) * SF_STR + c + 1] = acc[nt][3];
        }
    }
    __syncthreads();                 // W0 reads + K0 stores complete
    lw_issue(sm, sb, 1, tid);

    // scores0 (reads sF=K0)
#pragma unroll
    for (int it = 0; it < 4; it++) {
        int idx = tid + it * 512;
        int s = idx & 15, qi = (idx >> 4) & 3, h = (idx >> 6) & 3, e = idx >> 8;
        const float4* qv = (const float4*)&sIq[qi * 128 + h * 32];
        const float4* kv = (const float4*)&sF[(e * 16 + s) * SF_STR + h * 32];
        float dot = sIqb[qi * 4 + h];
#pragma unroll
        for (int d4 = 0; d4 < 8; d4++) {
            float4 q = qv[d4], k = kv[d4];
            dot += q.x * k.x + q.y * k.y + q.z * k.z + q.w * k.w;
        }
        sScr[idx] = dot * SCALE_INV;
    }
    cp_wait();
    __syncthreads();                 // scores0 done reading sF; W1 visible

    // ===== V0 = X@Wv0 + bv0 -> sF ; softmax0 in same region =====
#pragma unroll
    for (int j = 0; j < 8; j++)
#pragma unroll
        for (int q = 0; q < 4; q++) acc[j][q] = 0.f;
    gemm128(xh, xl, wh, wl, wid, lane, acc);
    {
        int r = rg * 16 + l4;
#pragma unroll
        for (int nt = 0; nt < 8; nt++) {
            int c = cg * 64 + nt * 8 + c2;
            sF[r * SF_STR + c]       = acc[nt][0] + sBias[c];
            sF[r * SF_STR + c + 1]   = acc[nt][1] + sBias[c + 1];
            sF[(r + 8) * SF_STR + c]     = acc[nt][2] + sBias[c];
            sF[(r + 8) * SF_STR + c + 1] = acc[nt][3] + sBias[c + 1];
        }
    }
    if (tid < 128) {                 // softmax0 (sScr closed last region)
        float* p = &sScr[tid * 16];
        float mx = p[0];
#pragma unroll
        for (int i = 1; i < 16; i++) mx = fmaxf(mx, p[i]);
        float sum = 0.f;
#pragma unroll
        for (int i = 0; i < 16; i++) { float ex = expf(p[i] - mx); p[i] = ex; sum += ex; }
        float inv = 1.f / sum;
#pragma unroll
        for (int i = 0; i < 16; i++) p[i] *= inv;
    }
    __syncthreads();
    lw_issue(sm, sb, 2, tid);

    // O0 = Iq + A @ V0f -> sSm (32 rows)
#pragma unroll
    for (int it = 0; it < 2; it++) {
        int idx = tid + it * 512;            // 1024 float4 items
        int d = (idx & 31) * 4, row = idx >> 5;
        int qi = row & 3, e = row >> 2, h = d >> 5;
        float4 o = *(const float4*)&sIq[qi * 128 + d];
        const float* A = &sScr[((e * 4 + h) * 4 + qi) * 16];
        const float* vv = &sF[(e * 16) * SF_STR + d];
#pragma unroll
        for (int s = 0; s < 16; s++) {
            float4 v = *(const float4*)&vv[s * SF_STR];
            float a = A[s];
            o.x += a * v.x; o.y += a * v.y; o.z += a * v.z; o.w += a * v.w;
        }
        *(float4*)&sSm[row * SF_STR + d] = o;
    }
    cp_wait();
    __syncthreads();                 // W2 visible; O0 complete

    // ===== Q1 = X@Wq1 + bq1 -> sF =====
#pragma unroll
    for (int j = 0; j < 8; j++)
#pragma unroll
        for (int q = 0; q < 4; q++) acc[j][q] = 0.f;
    gemm128(xh, xl, wh, wl, wid, lane, acc);
    {
        int r = rg * 16 + l4;
#pragma unroll
        for (int nt = 0; nt < 8; nt++) {
            int c = cg * 64 + nt * 8 + c2;
            sF[r * SF_STR + c]       = acc[nt][0] + sBias[2 * 128 + c];
            sF[r * SF_STR + c + 1]   = acc[nt][1] + sBias[2 * 128 + c + 1];
            sF[(r + 8) * SF_STR + c]     = acc[nt][2] + sBias[2 * 128 + c];
            sF[(r + 8) * SF_STR + c + 1] = acc[nt][3] + sBias[2 * 128 + c + 1];
        }
    }
    __syncthreads();                 // ALL X reads done (X dead)
    lw_issue(sm, sb, 3, tid);
    // O0 -> X image rows 0..31
#pragma unroll
    for (int it = 0; it < 2; it++) {
        int i = tid + it * 512;              // 1024 float4 items
        int r = i >> 5, c = (i & 31) * 4;
        img_st4(sm, r, c, *(const float4*)&sSm[r * SF_STR + c]);
    }
    cp_wait();
    __syncthreads();                 // O0 image + W3 visible

    // ===== T0 = O0@Wo0 ; Hset = O0 + relu(T0+bo0) -> image rows 0..31 =====
    acc32[0][0] = acc32[0][1] = acc32[0][2] = acc32[0][3] = 0.f;
    acc32[1][0] = acc32[1][1] = acc32[1][2] = acc32[1][3] = 0.f;
    gemm32(xh, xl, wh, wl, wid, lane, acc32);
    __syncthreads();                 // all O0-image reads done
    lw_issue(sm, sb, 4, tid);
    {
        int rt = wid >> 3, cg8 = wid & 7;
        int r = rt * 16 + l4;
#pragma unroll
        for (int nt = 0; nt < 2; nt++) {
            int c = cg8 * 16 + nt * 8 + c2;
            float v0 = sSm[r * SF_STR + c]     + fmaxf(acc32[nt][0] + sBias[128 + c], 0.f);
            float v1 = sSm[r * SF_STR + c + 1] + fmaxf(acc32[nt][1] + sBias[128 + c + 1], 0.f);
            int i0 = imgoff(r, c);
            *(uint32_t*)(sm + OFF_XH + i0) = bf2bits(v0, v1);
            float h0 = __bfloat162float(__float2bfloat16(v0));
            float h1 = __bfloat162float(__float2bfloat16(v1));
            *(uint32_t*)(sm + OFF_XL + i0) = bf2bits(v0 - h0, v1 - h1);
            float w0 = sSm[(r + 8) * SF_STR + c]     + fmaxf(acc32[nt][2] + sBias[128 + c], 0.f);
            float w1 = sSm[(r + 8) * SF_STR + c + 1] + fmaxf(acc32[nt][3] + sBias[128 + c + 1], 0.f);
            int i1 = imgoff(r + 8, c);
            *(uint32_t*)(sm + OFF_XH + i1) = bf2bits(w0, w1);
            float g0 = __bfloat162float(__float2bfloat16(w0));
            float g1 = __bfloat162float(__float2bfloat16(w1));
            *(uint32_t*)(sm + OFF_XL + i1) = bf2bits(w0 - g0, w1 - g1);
        }
    }
    cp_wait();
    __syncthreads();                 // Hset image + W4 visible

    // ===== K1 = Hset@Wk1 + bk1 -> sK1 (disjoint scratch; store in-region) =====
    acc32[0][0] = acc32[0][1] = acc32[0][2] = acc32[0][3] = 0.f;
    acc32[1][0] = acc32[1][1] = acc32[1][2] = acc32[1][3] = 0.f;
    gemm32(xh, xl, wh, wl, wid, lane, acc32);
    {
        int rt = wid >> 3, cg8 = wid & 7;
        int r = rt * 16 + l4;
#pragma unroll
        for (int nt = 0; nt < 2; nt++) {
            int c = cg8 * 16 + nt * 8 + c2;
            sK1[r * SF_STR + c]       = acc32[nt][0] + sBias[3 * 128 + c];
            sK1[r * SF_STR + c + 1]   = acc32[nt][1] + sBias[3 * 128 + c + 1];
            sK1[(r + 8) * SF_STR + c]     = acc32[nt][2] + sBias[3 * 128 + c];
            sK1[(r + 8) * SF_STR + c + 1] = acc32[nt][3] + sBias[3 * 128 + c + 1];
        }
    }
    __syncthreads();                 // W4 reads done
    lw_issue(sm, sb, 5, tid);
    cp_wait();
    __syncthreads();                 // W5 visible

    // ===== V1 = Hset@Wv1 + bv1 -> sSm (O0 dead; store in-region) =====
    acc32[0][0] = acc32[0][1] = acc32[0][2] = acc32[0][3] = 0.f;
    acc32[1][0] = acc32[1][1] = acc32[1][2] = acc32[1][3] = 0.f;
    gemm32(xh, xl, wh, wl, wid, lane, acc32);
    {
        int rt = wid >> 3, cg8 = wid & 7;
        int r = rt * 16 + l4;
#pragma unroll
        for (int nt = 0; nt < 2; nt++) {
            int c = cg8 * 16 + nt * 8 + c2;
            sSm[r * SF_STR + c]       = acc32[nt][0] + sBias[4 * 128 + c];
            sSm[r * SF_STR + c + 1]   = acc32[nt][1] + sBias[4 * 128 + c + 1];
            sSm[(r + 8) * SF_STR + c]     = acc32[nt][2] + sBias[4 * 128 + c];
            sSm[(r + 8) * SF_STR + c + 1] = acc32[nt][3] + sBias[4 * 128 + c + 1];
        }
    }
    __syncthreads();                 // W5 reads + V1f stores done
    lw_issue(sm, sb, 6, tid);

    // scores1 (reads sF=Q1, sK1)
#pragma unroll
    for (int it = 0; it < 4; it++) {
        int idx = tid + it * 512;
        int k = idx & 3, q = (idx >> 2) & 15, h = (idx >> 6) & 3, e = idx >> 8;
        const float4* qv = (const float4*)&sF[(e * 16 + q) * SF_STR + h * 32];
        const float4* kv = (const float4*)&sK1[(e * 4 + k) * SF_STR + h * 32];
        float dot = 0.f;
#pragma unroll
        for (int d4 = 0; d4 < 8; d4++) {
            float4 qq = qv[d4], kk = kv[d4];
            dot += qq.x * kk.x + qq.y * kk.y + qq.z * kk.z + qq.w * kk.w;
        }
        sScr[idx] = dot * SCALE_INV;
    }
    __syncthreads();
    {   // softmax1: 512 rows, one per thread
        float* p = &sScr[tid * 4];
        float mx = fmaxf(fmaxf(p[0], p[1]), fmaxf(p[2], p[3]));
        float e0 = expf(p[0] - mx), e1 = expf(p[1] - mx), e2 = expf(p[2] - mx), e3 = expf(p[3] - mx);
        float inv = 1.f / (e0 + e1 + e2 + e3);
        p[0] = e0 * inv; p[1] = e1 * inv; p[2] = e2 * inv; p[3] = e3 * inv;
    }
    __syncthreads();

    // O = Q1 + A1@V1f (V1f in sSm), fused sF update + X image write (K1f dead)
#pragma unroll
    for (int it = 0; it < 8; it++) {
        int idx = tid + it * 512;            // 4096 float4 items
        int d = (idx & 31) * 4, row = idx >> 5;
        int q = row & 15, e = row >> 4, h = d >> 5;
        float4 o = *(const float4*)&sF[row * SF_STR + d];
        const float* A = &sScr[((e * 4 + h) * 16 + q) * 4];
#pragma unroll
        for (int k = 0; k < 4; k++) {
            float4 v = *(const float4*)&sSm[(e * 4 + k) * SF_STR + d];
            float a = A[k];
            o.x += a * v.x; o.y += a * v.y; o.z += a * v.z; o.w += a * v.w;
        }
        *(float4*)&sF[row * SF_STR + d] = o;
        img_st4(sm, row, d, o);
    }
    cp_wait();
    __syncthreads();                 // O image + W6 visible

    // ===== T1 = O@Wo1 ; final = O + relu(T1+bo1) -> sF in place =====
#pragma unroll
    for (int j = 0; j < 8; j++)
#pragma unroll
        for (int q = 0; q < 4; q++) acc[j][q] = 0.f;
    gemm128(xh, xl, wh, wl, wid, lane, acc);
    {
        int r = rg * 16 + l4;
#pragma unroll
        for (int nt = 0; nt < 8; nt++) {
            int c = cg * 64 + nt * 8 + c2;
            sF[r * SF_STR + c]       += fmaxf(acc[nt][0] + sBias[5 * 128 + c], 0.f);
            sF[r * SF_STR + c + 1]   += fmaxf(acc[nt][1] + sBias[5 * 128 + c + 1], 0.f);
            sF[(r + 8) * SF_STR + c]     += fmaxf(acc[nt][2] + sBias[5 * 128 + c], 0.f);
            sF[(r + 8) * SF_STR + c + 1] += fmaxf(acc[nt][3] + sBias[5 * 128 + c + 1], 0.f);
        }
    }
    __syncthreads();

    // logits: first 256 threads, 2 per row x 3 cols
    if (tid < 256) {
        int r = tid >> 1, cb = (tid & 1) * 3;
        float a0 = sWo[768 + cb], a1 = sWo[768 + cb + 1], a2 = sWo[768 + cb + 2];
        const float4* xr = (const float4*)&sF[r * SF_STR];
#pragma unroll
        for (int k4 = 0; k4 < 32; k4++) {
            float4 x = xr[k4];
            const float* w0 = &sWo[(k4 * 4 + 0) * C_CLS + cb];
            const float* w1 = &sWo[(k4 * 4 + 1) * C_CLS + cb];
            const float* w2 = &sWo[(k4 * 4 + 2) * C_CLS + cb];
            const float* w3 = &sWo[(k4 * 4 + 3) * C_CLS + cb];
            a0 += x.x * w0[0] + x.y * w1[0] + x.z * w2[0] + x.w * w3[0];
            a1 += x.x * w0[1] + x.y * w1[1] + x.z * w2[1] + x.w * w3[1];
            a2 += x.x * w0[2] + x.y * w1[2] + x.z * w2[2] + x.w * w3[2];
        }
        long long off = (long long)(rowbase + r) * C_CLS + cb;
        if (off + 2 < out_capacity) {
            out[off] = a0; out[off + 1] = a1; out[off + 2] = a2;
        }
    }
    long long lab_base = (long long)E_EDGES * S_MEM * C_CLS;
    if (out_capacity >= lab_base + (long long)E_EDGES * S_MEM && tid < ROWS) {
        out[lab_base + rowbase + tid] = (float)labels[rowbase + tid];
    }
}

extern "C" void kernel_launch(void* const* d_in, const int* in_sizes, int n_in,
                              void* d_out, int out_size) {
    const float* Ws[8] = {0,0,0,0,0,0,0,0};
    const float* Bs[8] = {0,0,0,0,0,0,0,0};
    const float* vfeat = 0; const float* Iin = 0;
    const float* Wout = 0;  const float* bout = 0;
    const int* member_idx = 0; const int* labels = 0;
    int wi = 0, bi = 0, n_nodes = 500000;
    for (int i = 0; i < n_in; i++) {
        int sz = in_sizes[i];
        if (sz == 500000 * 128)      { vfeat = (const float*)d_in[i]; n_nodes = sz / D_DIM; }
        else if (sz == E_EDGES * S_MEM) {
            if (!member_idx) member_idx = (const int*)d_in[i];
            else if (!labels) labels = (const int*)d_in[i];
        }
        else if (sz == M_IND * D_DIM) Iin = (const float*)d_in[i];
        else if (sz == D_DIM * C_CLS) Wout = (const float*)d_in[i];
        else if (sz == C_CLS)         bout = (const float*)d_in[i];
        else if (sz == D_DIM * D_DIM) { if (wi < 8) Ws[wi++] = (const float*)d_in[i]; }
        else if (sz == D_DIM)         { if (bi < 8) Bs[bi++] = (const float*)d_in[i]; }
    }
    if (!vfeat || !member_idx || !labels || !Iin || !Wout || !bout || wi != 8 || bi != 8) {
        vfeat = (const float*)d_in[0]; member_idx = (const int*)d_in[1];
        labels = (const int*)d_in[2];  Iin = (const float*)d_in[3];
        Wout = (const float*)d_in[4];  bout = (const float*)d_in[5];
        for (int j = 0; j < 8; j++) { Ws[j] = (const float*)d_in[6 + 2 * j]; Bs[j] = (const float*)d_in[7 + 2 * j]; }
        n_nodes = in_sizes[0] / D_DIM;
    }
    const float *Wq0 = Ws[0], *Wk0 = Ws[1], *Wv0 = Ws[2], *Wo0 = Ws[3];
    const float *Wq1 = Ws[4], *Wk1 = Ws[5], *Wv1 = Ws[6], *Wo1 = Ws[7];
    const float *bq0 = Bs[0], *bk0 = Bs[1], *bv0 = Bs[2], *bo0 = Bs[3];
    const float *bq1 = Bs[4], *bk1 = Bs[5], *bv1 = Bs[6], *bo1 = Bs[7];

    cudaFuncSetAttribute(whatsnet_mma, cudaFuncAttributeMaxDynamicSharedMemorySize, SMEM_TOTAL);

    iq_kernel<<<2, 256>>>(Iin, Wq0, bq0);
    iqb_kernel<<<1, 32>>>(bk0);
    wconv_kernel<<<7, 256>>>(Wk0, Wv0, Wq1, Wo0, Wk1, Wv1, Wo1);

    whatsnet_mma<<<E_EDGES * S_MEM / ROWS, NTH, SMEM_TOTAL>>>(
        vfeat, member_idx, labels, Wout, bout,
        bv0, bo0, bq1, bk1, bv1, bo1,
        (float*)d_out, n_nodes, (long long)out_size);
}